// round 6
// baseline (speedup 1.0000x reference)
#include <cuda_runtime.h>
#include <cuda_bf16.h>
#include <cstdint>
#include <cstddef>
#include <math.h>

#define N_  262144
#define C_  200
#define HID_ 128
#define S_  4096
#define EA_ 65536
#define EM_ 2097152
#define NC_ 16

// ---------------- device scratch ----------------
__device__ float g_x0[(size_t)N_ * HID_];
__device__ float g_t0[(size_t)N_ * HID_];
__device__ float g_pf[(size_t)N_ * HID_];
__device__ float g_Q [(size_t)N_ * HID_];
__device__ float g_V [(size_t)N_ * HID_];

__device__ float g_hp[S_ * HID_];
__device__ float g_h [S_ * HID_];
__device__ float g_xs[S_ * HID_];
__device__ float g_cA[S_ * HID_];
__device__ float g_cB[S_ * HID_];

__device__ int   g_hist[N_];
__device__ int   g_aux[1024];
__device__ int   g_peOff[N_ + 1];
__device__ int   g_peCur[N_];
__device__ int   g_peDst[EM_];
__device__ int   g_aOff[S_ + 1];
__device__ int   g_aCur[S_];
__device__ int   g_aSrc[EA_];
__device__ float g_aW [EA_];
__device__ int   g_pOff[S_ + 1];
__device__ int   g_pCur[S_];
__device__ int   g_pSort[N_];
__device__ float g_stats[256];

__device__ __align__(256) unsigned char g_Bimg[720896];
__device__ float g_biasQV[512];

// ---------------- split helpers ----------------
__device__ __forceinline__ void split4(float4 v, uint32_t& h01, uint32_t& h23,
                                       uint32_t& l01, uint32_t& l23) {
    __nv_bfloat16 h0 = __float2bfloat16(v.x), h1 = __float2bfloat16(v.y);
    __nv_bfloat16 h2 = __float2bfloat16(v.z), h3 = __float2bfloat16(v.w);
    __nv_bfloat16 l0 = __float2bfloat16(v.x - __bfloat162float(h0));
    __nv_bfloat16 l1 = __float2bfloat16(v.y - __bfloat162float(h1));
    __nv_bfloat16 l2 = __float2bfloat16(v.z - __bfloat162float(h2));
    __nv_bfloat16 l3 = __float2bfloat16(v.w - __bfloat162float(h3));
    h01 = ((uint32_t)__bfloat16_as_ushort(h1) << 16) | (uint32_t)__bfloat16_as_ushort(h0);
    h23 = ((uint32_t)__bfloat16_as_ushort(h3) << 16) | (uint32_t)__bfloat16_as_ushort(h2);
    l01 = ((uint32_t)__bfloat16_as_ushort(l1) << 16) | (uint32_t)__bfloat16_as_ushort(l0);
    l23 = ((uint32_t)__bfloat16_as_ushort(l3) << 16) | (uint32_t)__bfloat16_as_ushort(l2);
}

__device__ __forceinline__ void mma16816(float* c, const uint32_t* a, const uint32_t* b) {
    asm volatile(
        "mma.sync.aligned.m16n8k16.row.col.f32.bf16.bf16.f32 "
        "{%0,%1,%2,%3}, {%4,%5,%6,%7}, {%8,%9}, {%0,%1,%2,%3};"
        : "+f"(c[0]), "+f"(c[1]), "+f"(c[2]), "+f"(c[3])
        : "r"(a[0]), "r"(a[1]), "r"(a[2]), "r"(a[3]), "r"(b[0]), "r"(b[1]));
}

// ---------------- prep kernels ----------------
__global__ void prep_w_kernel(const float* __restrict__ W, int Kreal, int Kp,
                              __nv_bfloat16* __restrict__ img) {
    int idx = blockIdx.x * 256 + threadIdx.x;
    int kq = Kp >> 2;
    if (idx >= 128 * kq) return;
    int n = idx / kq;
    int k = (idx - n * kq) * 4;
    float4 v;
    v.x = (k + 0 < Kreal) ? W[(k + 0) * 128 + n] : 0.f;
    v.y = (k + 1 < Kreal) ? W[(k + 1) * 128 + n] : 0.f;
    v.z = (k + 2 < Kreal) ? W[(k + 2) * 128 + n] : 0.f;
    v.w = (k + 3 < Kreal) ? W[(k + 3) * 128 + n] : 0.f;
    uint32_t h01, h23, l01, l23;
    split4(v, h01, h23, l01, l23);
    *(uint2*)(img + (size_t)n * Kp + k)                    = make_uint2(h01, h23);
    *(uint2*)(img + (size_t)128 * Kp + (size_t)n * Kp + k) = make_uint2(l01, l23);
}

__global__ void prep_qv_kernel(const float* __restrict__ Wq, const float* __restrict__ Wv,
                               const float* __restrict__ bq, const float* __restrict__ bv,
                               __nv_bfloat16* __restrict__ img, float* __restrict__ biasOut) {
    int idx = blockIdx.x * 256 + threadIdx.x;
    if (idx >= 256 * 32) return;
    int n = idx >> 5;
    int k = (idx & 31) * 4;
    const float* W = (n < 128) ? Wq : Wv;
    int nn = (n < 128) ? n : n - 128;
    int h = nn >> 6, col = nn & 63;
    float4 v;
    v.x = W[((h * 128) + k + 0) * 64 + col];
    v.y = W[((h * 128) + k + 1) * 64 + col];
    v.z = W[((h * 128) + k + 2) * 64 + col];
    v.w = W[((h * 128) + k + 3) * 64 + col];
    uint32_t h01, h23, l01, l23;
    split4(v, h01, h23, l01, l23);
    *(uint2*)(img + (size_t)n * 128 + k)                     = make_uint2(h01, h23);
    *(uint2*)(img + (size_t)256 * 128 + (size_t)n * 128 + k) = make_uint2(l01, l23);
    if ((idx & 31) == 0) biasOut[n] = (n < 128) ? bq[h * 64 + col] : bv[h * 64 + col];
}

// ---------------- warp-MMA GEMM ----------------
#define LDA 72
#define SM_GEMM (4 * 128 * LDA * 2 + 512)
__global__ __launch_bounds__(256) void gemm_mma_kernel(
    const float* __restrict__ A, int Kreal, int Kp,
    const __nv_bfloat16* __restrict__ Bimg, int Nc,
    const float* __restrict__ bias,
    float* __restrict__ outA, float* __restrict__ outB) {
    extern __shared__ char smem[];
    __nv_bfloat16* Ah = (__nv_bfloat16*)smem;          // [128][LDA]
    __nv_bfloat16* Al = Ah + 128 * LDA;
    __nv_bfloat16* Bh = Al + 128 * LDA;
    __nv_bfloat16* Bl = Bh + 128 * LDA;
    float* bsm = (float*)(Bl + 128 * LDA);
    int tid = threadIdx.x;
    int lane = tid & 31, wid = tid >> 5;
    int wm = wid & 3, wn = wid >> 2;                   // 4 x 2 warps
    long rowBase = (long)blockIdx.x * 128;
    int nh = blockIdx.y;
    const __nv_bfloat16* BsrcH = Bimg + (size_t)(nh * 128) * Kp;
    const __nv_bfloat16* BsrcL = Bimg + (size_t)Nc * Kp + (size_t)(nh * 128) * Kp;
    if (tid < 128) bsm[tid] = bias[nh * 128 + tid];

    float acc[2][8][4];
#pragma unroll
    for (int t = 0; t < 2; t++)
#pragma unroll
        for (int j = 0; j < 8; j++)
#pragma unroll
            for (int q = 0; q < 4; q++) acc[t][j][q] = 0.f;

    for (int k0 = 0; k0 < Kp; k0 += 64) {
        __syncthreads();
        // B: async copy 128 n-rows x 64 k bf16, hi+lo planes (overlaps A convert below)
#pragma unroll
        for (int i = 0; i < 8; i++) {
            int flat = tid + i * 256;
            int plane = flat >> 10;
            int r = (flat >> 3) & 127;
            int q = flat & 7;
            const __nv_bfloat16* src = (plane ? BsrcL : BsrcH) + (size_t)r * Kp + k0 + q * 8;
            __nv_bfloat16* dst = (plane ? Bl : Bh) + r * LDA + q * 8;
            uint32_t da = (uint32_t)__cvta_generic_to_shared(dst);
            asm volatile("cp.async.ca.shared.global [%0], [%1], 16;" :: "r"(da), "l"(src));
        }
        asm volatile("cp.async.commit_group;" ::: "memory");
        // A: 128 rows x 64 k fp32 -> split into Ah/Al
#pragma unroll
        for (int i = 0; i < 8; i++) {
            int flat = tid + i * 256;
            int row = flat >> 4;
            int c = (flat & 15) * 4;
            int k = k0 + c;
            float4 v = make_float4(0.f, 0.f, 0.f, 0.f);
            if (k < Kreal) {
                const float* ap = A + (rowBase + row) * (long)Kreal + k;
                if (k + 3 < Kreal) v = *(const float4*)ap;
                else {
                    v.x = ap[0];
                    if (k + 1 < Kreal) v.y = ap[1];
                    if (k + 2 < Kreal) v.z = ap[2];
                }
            }
            uint32_t h01, h23, l01, l23;
            split4(v, h01, h23, l01, l23);
            *(uint2*)(Ah + row * LDA + c) = make_uint2(h01, h23);
            *(uint2*)(Al + row * LDA + c) = make_uint2(l01, l23);
        }
        asm volatile("cp.async.wait_group 0;" ::: "memory");
        __syncthreads();

#pragma unroll
        for (int ks = 0; ks < 4; ks++) {
            int kk = ks * 16;
            uint32_t ah[2][4], al[2][4];
#pragma unroll
            for (int t = 0; t < 2; t++) {
                int r0 = wm * 32 + t * 16 + (lane >> 2);
                int cA = kk + (lane & 3) * 2;
                ah[t][0] = *(const uint32_t*)(Ah + r0 * LDA + cA);
                ah[t][1] = *(const uint32_t*)(Ah + (r0 + 8) * LDA + cA);
                ah[t][2] = *(const uint32_t*)(Ah + r0 * LDA + cA + 8);
                ah[t][3] = *(const uint32_t*)(Ah + (r0 + 8) * LDA + cA + 8);
                al[t][0] = *(const uint32_t*)(Al + r0 * LDA + cA);
                al[t][1] = *(const uint32_t*)(Al + (r0 + 8) * LDA + cA);
                al[t][2] = *(const uint32_t*)(Al + r0 * LDA + cA + 8);
                al[t][3] = *(const uint32_t*)(Al + (r0 + 8) * LDA + cA + 8);
            }
            uint32_t bh[8][2], bl[8][2];
#pragma unroll
            for (int j = 0; j < 8; j++) {
                int cn = wn * 64 + j * 8 + (lane >> 2);
                int cB = kk + (lane & 3) * 2;
                bh[j][0] = *(const uint32_t*)(Bh + cn * LDA + cB);
                bh[j][1] = *(const uint32_t*)(Bh + cn * LDA + cB + 8);
                bl[j][0] = *(const uint32_t*)(Bl + cn * LDA + cB);
                bl[j][1] = *(const uint32_t*)(Bl + cn * LDA + cB + 8);
            }
#pragma unroll
            for (int t = 0; t < 2; t++)
#pragma unroll
                for (int j = 0; j < 8; j++) {
                    mma16816(acc[t][j], ah[t], bh[j]);
                    mma16816(acc[t][j], al[t], bh[j]);
                    mma16816(acc[t][j], ah[t], bl[j]);
                }
        }
    }

    float* outP = (nh == 0) ? outA : outB;
#pragma unroll
    for (int t = 0; t < 2; t++) {
        long r0 = rowBase + wm * 32 + t * 16 + (lane >> 2);
#pragma unroll
        for (int j = 0; j < 8; j++) {
            int cloc = wn * 64 + j * 8 + (lane & 3) * 2;
            float2 v0 = make_float2(acc[t][j][0] + bsm[cloc], acc[t][j][1] + bsm[cloc + 1]);
            float2 v1 = make_float2(acc[t][j][2] + bsm[cloc], acc[t][j][3] + bsm[cloc + 1]);
            *(float2*)(outP + r0 * 128 + cloc)       = v0;
            *(float2*)(outP + (r0 + 8) * 128 + cloc) = v1;
        }
    }
}

// ---------------- utilities ----------------
__global__ void zero_kernel(int* p, int n) {
    int i = blockIdx.x * blockDim.x + threadIdx.x;
    if (i < n) p[i] = 0;
}
__global__ void zerof_kernel(float* p, int n) {
    int i = blockIdx.x * blockDim.x + threadIdx.x;
    if (i < n) p[i] = 0.f;
}

__global__ void hist_kernel(const int* __restrict__ keys, int n, int* __restrict__ hist) {
    int i = blockIdx.x * blockDim.x + threadIdx.x;
    if (i < n) atomicAdd(&hist[keys[i]], 1);
}

__global__ void scan_block_kernel(const int* __restrict__ in, int n,
                                  int* __restrict__ excl_out, int* __restrict__ bsum) {
    __shared__ int sh[1024];
    int tid = threadIdx.x;
    int idx = blockIdx.x * 1024 + tid;
    int v = (idx < n) ? in[idx] : 0;
    sh[tid] = v;
    __syncthreads();
    for (int off = 1; off < 1024; off <<= 1) {
        int t = (tid >= off) ? sh[tid - off] : 0;
        __syncthreads();
        sh[tid] += t;
        __syncthreads();
    }
    if (idx < n) excl_out[idx] = sh[tid] - v;
    if (tid == 1023) bsum[blockIdx.x] = sh[tid];
}

__global__ void scan_aux_kernel(int* aux, int nb) {
    __shared__ int sh[1024];
    int tid = threadIdx.x;
    int v = (tid < nb) ? aux[tid] : 0;
    sh[tid] = v;
    __syncthreads();
    for (int off = 1; off < 1024; off <<= 1) {
        int t = (tid >= off) ? sh[tid - off] : 0;
        __syncthreads();
        sh[tid] += t;
        __syncthreads();
    }
    if (tid < nb) aux[tid] = sh[tid] - v;
}

__global__ void scan_add_kernel(int* off, int n, const int* __restrict__ aux,
                                int* __restrict__ cursor, int total) {
    int idx = blockIdx.x * blockDim.x + threadIdx.x;
    if (idx < n) {
        int v = off[idx] + aux[idx >> 10];
        off[idx] = v;
        cursor[idx] = v;
    }
    if (idx == 0) off[n] = total;
}

__global__ void scatter_edge_kernel(const int* __restrict__ src, const int* __restrict__ dst,
                                    int n, int* __restrict__ cur, int* __restrict__ outDst) {
    int i = blockIdx.x * blockDim.x + threadIdx.x;
    if (i < n) {
        int p = atomicAdd(&cur[src[i]], 1);
        outDst[p] = dst[i];
    }
}

__global__ void scatter_aedge_kernel(const int* __restrict__ dstKey, const int* __restrict__ srcVal,
                                     const float* __restrict__ wVal, int n,
                                     int* __restrict__ cur, int* __restrict__ outSrc,
                                     float* __restrict__ outW) {
    int i = blockIdx.x * blockDim.x + threadIdx.x;
    if (i < n) {
        int p = atomicAdd(&cur[dstKey[i]], 1);
        outSrc[p] = srcVal[i];
        outW[p]   = wVal[i];
    }
}

__global__ void scatter_pix_kernel(const int* __restrict__ seg, int n,
                                   int* __restrict__ cur, int* __restrict__ outPix) {
    int i = blockIdx.x * blockDim.x + threadIdx.x;
    if (i < n) {
        int p = atomicAdd(&cur[seg[i]], 1);
        outPix[p] = i;
    }
}

// ---------------- BatchNorm ----------------
__global__ __launch_bounds__(256) void bnstats_kernel(const float* __restrict__ X, int M,
                                                      float* __restrict__ stats) {
    int lane = threadIdx.x & 31;
    int rs = threadIdx.x >> 5;
    float4 s = make_float4(0.f, 0.f, 0.f, 0.f);
    float4 q = make_float4(0.f, 0.f, 0.f, 0.f);
    for (long r = blockIdx.x * 8 + rs; r < M; r += (long)gridDim.x * 8) {
        float4 v = *(const float4*)(X + r * HID_ + lane * 4);
        s.x += v.x; s.y += v.y; s.z += v.z; s.w += v.w;
        q.x += v.x * v.x; q.y += v.y * v.y; q.z += v.z * v.z; q.w += v.w * v.w;
    }
    __shared__ float shs[8][HID_];
    __shared__ float shq[8][HID_];
    shs[rs][lane * 4 + 0] = s.x; shs[rs][lane * 4 + 1] = s.y;
    shs[rs][lane * 4 + 2] = s.z; shs[rs][lane * 4 + 3] = s.w;
    shq[rs][lane * 4 + 0] = q.x; shq[rs][lane * 4 + 1] = q.y;
    shq[rs][lane * 4 + 2] = q.z; shq[rs][lane * 4 + 3] = q.w;
    __syncthreads();
    if (threadIdx.x < HID_) {
        int c = threadIdx.x;
        float ss = 0.f, qq = 0.f;
#pragma unroll
        for (int r = 0; r < 8; r++) { ss += shs[r][c]; qq += shq[r][c]; }
        atomicAdd(&stats[c], ss);
        atomicAdd(&stats[HID_ + c], qq);
    }
}

__global__ void bnprep_kernel(float* stats, const float* __restrict__ g,
                              const float* __restrict__ b, float invM) {
    int c = threadIdx.x;
    float m = stats[c] * invM;
    float var = stats[HID_ + c] * invM - m * m;
    float w = rsqrtf(var + 1e-5f);
    float sc = w * g[c];
    stats[HID_ + c] = sc;
    stats[c] = b[c] - m * sc;
}

__global__ void bnapply_kernel(const float* __restrict__ X, float* __restrict__ Y,
                               const float* __restrict__ stats, long M, int lrelu) {
    long idx = (long)blockIdx.x * blockDim.x + threadIdx.x;
    long total = M * 32;
    if (idx >= total) return;
    int c4 = (int)(idx & 31);
    float4 v = *(const float4*)(X + idx * 4);
    float in[4] = {v.x, v.y, v.z, v.w};
    float o[4];
#pragma unroll
    for (int j = 0; j < 4; j++) {
        int c = c4 * 4 + j;
        float y = in[j] * stats[HID_ + c] + stats[c];
        if (lrelu) y = (y >= 0.f) ? y : 0.01f * y;
        o[j] = y;
    }
    *(float4*)(Y + idx * 4) = make_float4(o[0], o[1], o[2], o[3]);
}

// ---------------- LayerNorm per 64-wide head ----------------
__global__ __launch_bounds__(256) void ln_kernel(float* __restrict__ Q) {
    int wid = threadIdx.x >> 5, lane = threadIdx.x & 31;
    long row = (long)blockIdx.x * 8 + wid;
    float4 v = *(float4*)(Q + row * HID_ + lane * 4);
    float s = v.x + v.y + v.z + v.w;
    float q = v.x * v.x + v.y * v.y + v.z * v.z + v.w * v.w;
#pragma unroll
    for (int o = 8; o >= 1; o >>= 1) {
        s += __shfl_xor_sync(0xffffffffu, s, o);
        q += __shfl_xor_sync(0xffffffffu, q, o);
    }
    float m = s * (1.0f / 64.0f);
    float var = q * (1.0f / 64.0f) - m * m;
    float w = rsqrtf(var + 1e-5f);
    v.x = (v.x - m) * w; v.y = (v.y - m) * w;
    v.z = (v.z - m) * w; v.w = (v.w - m) * w;
    *(float4*)(Q + row * HID_ + lane * 4) = v;
}

// ---------------- fused per-src softmax attention ----------------
#define MAXE 64
__global__ __launch_bounds__(256) void attn_kernel(
    const float* __restrict__ Q, const float* __restrict__ V,
    const int* __restrict__ off, const int* __restrict__ dsts,
    float* __restrict__ out) {
    __shared__ float she[8][MAXE][2];
    int wid = threadIdx.x >> 5, lane = threadIdx.x & 31;
    int src = blockIdx.x * 8 + wid;
    int o0 = off[src], o1 = off[src + 1];
    int deg = o1 - o0;
    int half = lane >> 4;
    float4 qs = *(const float4*)(Q + (long)src * HID_ + lane * 4);
    float z = 0.f;
    bool cached = (deg <= MAXE);
    for (int i = 0; i < deg; i++) {
        int d = dsts[o0 + i];
        float4 qd = *(const float4*)(Q + (long)d * HID_ + lane * 4);
        float p = qs.x * qd.x + qs.y * qd.y + qs.z * qd.z + qs.w * qd.w;
        p += __shfl_xor_sync(0xffffffffu, p, 8);
        p += __shfl_xor_sync(0xffffffffu, p, 4);
        p += __shfl_xor_sync(0xffffffffu, p, 2);
        p += __shfl_xor_sync(0xffffffffu, p, 1);
        float e = __expf(p * (1.0f / HID_));
        z += e;
        if (cached && (lane & 15) == 0) she[wid][i][half] = e;
    }
    __syncwarp();
    float invz = (deg > 0) ? 1.0f / z : 0.f;
    float4 acc = make_float4(0.f, 0.f, 0.f, 0.f);
    for (int i = 0; i < deg; i++) {
        int d = dsts[o0 + i];
        float e;
        if (cached) {
            e = she[wid][i][half];
        } else {
            float4 qd = *(const float4*)(Q + (long)d * HID_ + lane * 4);
            float p = qs.x * qd.x + qs.y * qd.y + qs.z * qd.z + qs.w * qd.w;
            p += __shfl_xor_sync(0xffffffffu, p, 8);
            p += __shfl_xor_sync(0xffffffffu, p, 4);
            p += __shfl_xor_sync(0xffffffffu, p, 2);
            p += __shfl_xor_sync(0xffffffffu, p, 1);
            e = __expf(p * (1.0f / HID_));
        }
        float a = e * invz;
        float4 vd = *(const float4*)(V + (long)d * HID_ + lane * 4);
        acc.x += a * vd.x; acc.y += a * vd.y;
        acc.z += a * vd.z; acc.w += a * vd.w;
    }
    *(float4*)(out + (long)src * HID_ + lane * 4) = acc;
}

// ---------------- superpixel mean pooling ----------------
__global__ __launch_bounds__(256) void pool_kernel(const float* __restrict__ X,
                                                   const int* __restrict__ off,
                                                   const int* __restrict__ pix,
                                                   float* __restrict__ hp) {
    int wid = threadIdx.x >> 5, lane = threadIdx.x & 31;
    int s = blockIdx.x * 8 + wid;
    int o0 = off[s], o1 = off[s + 1];
    float4 acc = make_float4(0.f, 0.f, 0.f, 0.f);
    for (int i = o0; i < o1; i++) {
        int p = pix[i];
        float4 v = *(const float4*)(X + (long)p * HID_ + lane * 4);
        acc.x += v.x; acc.y += v.y; acc.z += v.z; acc.w += v.w;
    }
    int deg = o1 - o0;
    float inv = 1.0f / (float)(deg > 0 ? deg : 1);
    acc.x *= inv; acc.y *= inv; acc.z *= inv; acc.w *= inv;
    *(float4*)(hp + (long)s * HID_ + lane * 4) = acc;
}

// ---------------- weighted sparse prop (dst-CSR) ----------------
__global__ __launch_bounds__(256) void prop_kernel(const float* __restrict__ X,
                                                   const int* __restrict__ off,
                                                   const int* __restrict__ srcs,
                                                   const float* __restrict__ w,
                                                   const float* __restrict__ add, float scale,
                                                   float* __restrict__ out) {
    int wid = threadIdx.x >> 5, lane = threadIdx.x & 31;
    int d = blockIdx.x * 8 + wid;
    int o0 = off[d], o1 = off[d + 1];
    float4 acc = make_float4(0.f, 0.f, 0.f, 0.f);
    for (int i = o0; i < o1; i++) {
        int sN = srcs[i];
        float ww = w[i];
        float4 v = *(const float4*)(X + (long)sN * HID_ + lane * 4);
        acc.x += ww * v.x; acc.y += ww * v.y;
        acc.z += ww * v.z; acc.w += ww * v.w;
    }
    if (add) {
        float4 a = *(const float4*)(add + (long)d * HID_ + lane * 4);
        acc.x = (acc.x + a.x) * scale; acc.y = (acc.y + a.y) * scale;
        acc.z = (acc.z + a.z) * scale; acc.w = (acc.w + a.w) * scale;
    }
    *(float4*)(out + (long)d * HID_ + lane * 4) = acc;
}

// ---------------- final: softmax((pf + hp[seg]) @ W + b) ----------------
__global__ __launch_bounds__(256) void final_kernel(const float* __restrict__ PF,
                                                    const float* __restrict__ HP,
                                                    const int* __restrict__ seg,
                                                    const float* __restrict__ W,
                                                    const float* __restrict__ bias,
                                                    float* __restrict__ out) {
    __shared__ float Ws[HID_ * NC_];
    __shared__ float bs[NC_];
    for (int i = threadIdx.x; i < HID_ * NC_; i += 256) Ws[i] = W[i];
    if (threadIdx.x < NC_) bs[threadIdx.x] = bias[threadIdx.x];
    __syncthreads();
    int wid = threadIdx.x >> 5, lane = threadIdx.x & 31;
    long row = (long)blockIdx.x * 8 + wid;
    int sg = seg[row];
    float4 p4 = *(const float4*)(PF + row * HID_ + lane * 4);
    float4 h4 = *(const float4*)(HP + (long)sg * HID_ + lane * 4);
    float h[4] = {p4.x + h4.x, p4.y + h4.y, p4.z + h4.z, p4.w + h4.w};
    float l[NC_];
#pragma unroll
    for (int c = 0; c < NC_; c++) {
        l[c] = h[0] * Ws[(lane * 4 + 0) * NC_ + c] + h[1] * Ws[(lane * 4 + 1) * NC_ + c] +
               h[2] * Ws[(lane * 4 + 2) * NC_ + c] + h[3] * Ws[(lane * 4 + 3) * NC_ + c];
    }
#pragma unroll
    for (int o = 16; o >= 1; o >>= 1) {
#pragma unroll
        for (int c = 0; c < NC_; c++) l[c] += __shfl_xor_sync(0xffffffffu, l[c], o);
    }
    float mx = -1e30f;
#pragma unroll
    for (int c = 0; c < NC_; c++) {
        l[c] += bs[c];
        mx = fmaxf(mx, l[c]);
    }
    float sum = 0.f;
#pragma unroll
    for (int c = 0; c < NC_; c++) {
        l[c] = __expf(l[c] - mx);
        sum += l[c];
    }
    float inv = 1.0f / sum;
    if (lane < NC_) {
        float v = 0.f;
#pragma unroll
        for (int c = 0; c < NC_; c++)
            if (lane == c) v = l[c];
        out[row * NC_ + lane] = v * inv;
    }
}

// ---------------- host orchestration ----------------
static void run_bn(const float* X, float* Y, const float* g, const float* b,
                   float* stats, long M, int lrelu) {
    zerof_kernel<<<1, 256>>>(stats, 256);
    int nb = (M >= 100000) ? 1024 : 16;
    bnstats_kernel<<<nb, 256>>>(X, (int)M, stats);
    bnprep_kernel<<<1, 128>>>(stats, g, b, 1.0f / (float)M);
    long total = M * 32;
    bnapply_kernel<<<(int)((total + 255) / 256), 256>>>(X, Y, stats, M, lrelu);
}

extern "C" void kernel_launch(void* const* d_in, const int* in_sizes, int n_in,
                              void* d_out, int out_size) {
    const float* x      = (const float*)d_in[0];
    const int*   seg    = (const int*)d_in[1];
    const int*   a_src  = (const int*)d_in[2];
    const int*   a_dst  = (const int*)d_in[3];
    const float* a_w    = (const float*)d_in[4];
    const int*   m_src  = (const int*)d_in[5];
    const int*   m_dst  = (const int*)d_in[6];
    const float* pre_W  = (const float*)d_in[7];
    const float* pre_b  = (const float*)d_in[8];
    const float* bn0_g  = (const float*)d_in[9];
    const float* bn0_b  = (const float*)d_in[10];
    const float* sf_W   = (const float*)d_in[11];
    const float* sf_b   = (const float*)d_in[12];
    const float* sf_g   = (const float*)d_in[13];
    const float* sf_beta= (const float*)d_in[14];
    const float* pf_Wv  = (const float*)d_in[15];
    const float* pf_bv  = (const float*)d_in[16];
    const float* pf_Wq  = (const float*)d_in[17];
    const float* pf_bq  = (const float*)d_in[18];
    const float* pf_g   = (const float*)d_in[19];
    const float* pf_beta= (const float*)d_in[20];
    const float* out_W  = (const float*)d_in[21];
    const float* out_b  = (const float*)d_in[22];
    float* out = (float*)d_out;

    float *p_x0, *p_t0, *p_pf, *p_Q, *p_V, *p_hp, *p_h, *p_xs, *p_cA, *p_cB, *p_aW, *p_stats, *p_biasQV;
    int *p_hist, *p_aux, *p_peOff, *p_peCur, *p_peDst, *p_aOff, *p_aCur, *p_aSrc;
    int *p_pOff, *p_pCur, *p_pSort;
    unsigned char* p_img;
    cudaGetSymbolAddress((void**)&p_x0, g_x0);
    cudaGetSymbolAddress((void**)&p_t0, g_t0);
    cudaGetSymbolAddress((void**)&p_pf, g_pf);
    cudaGetSymbolAddress((void**)&p_Q,  g_Q);
    cudaGetSymbolAddress((void**)&p_V,  g_V);
    cudaGetSymbolAddress((void**)&p_hp, g_hp);
    cudaGetSymbolAddress((void**)&p_h,  g_h);
    cudaGetSymbolAddress((void**)&p_xs, g_xs);
    cudaGetSymbolAddress((void**)&p_cA, g_cA);
    cudaGetSymbolAddress((void**)&p_cB, g_cB);
    cudaGetSymbolAddress((void**)&p_aW, g_aW);
    cudaGetSymbolAddress((void**)&p_stats, g_stats);
    cudaGetSymbolAddress((void**)&p_hist, g_hist);
    cudaGetSymbolAddress((void**)&p_aux, g_aux);
    cudaGetSymbolAddress((void**)&p_peOff, g_peOff);
    cudaGetSymbolAddress((void**)&p_peCur, g_peCur);
    cudaGetSymbolAddress((void**)&p_peDst, g_peDst);
    cudaGetSymbolAddress((void**)&p_aOff, g_aOff);
    cudaGetSymbolAddress((void**)&p_aCur, g_aCur);
    cudaGetSymbolAddress((void**)&p_aSrc, g_aSrc);
    cudaGetSymbolAddress((void**)&p_pOff, g_pOff);
    cudaGetSymbolAddress((void**)&p_pCur, g_pCur);
    cudaGetSymbolAddress((void**)&p_pSort, g_pSort);
    cudaGetSymbolAddress((void**)&p_img, g_Bimg);
    cudaGetSymbolAddress((void**)&p_biasQV, g_biasQV);

    cudaFuncSetAttribute(gemm_mma_kernel, cudaFuncAttributeMaxDynamicSharedMemorySize, SM_GEMM);

    __nv_bfloat16* img_pre = (__nv_bfloat16*)p_img;                  // Kp=256, Nc=128
    __nv_bfloat16* img_qv0 = (__nv_bfloat16*)(p_img + 131072);       // Kp=128, Nc=256
    __nv_bfloat16* img_qv1 = (__nv_bfloat16*)(p_img + 262144);
    __nv_bfloat16* img_sf  = (__nv_bfloat16*)(p_img + 393216);       // Kp=128, Nc=128

    // ---- launches 1-3: prep images needed by the pre-GEMM ----
    prep_w_kernel<<<32, 256>>>(pre_W, C_, 256, img_pre);
    prep_qv_kernel<<<32, 256>>>(pf_Wq, pf_Wv, pf_bq, pf_bv, img_qv0, p_biasQV);
    prep_qv_kernel<<<32, 256>>>(pf_Wq + (size_t)2 * HID_ * 64, pf_Wv + (size_t)2 * HID_ * 64,
                                pf_bq + HID_, pf_bv + HID_, img_qv1, p_biasQV + 256);

    // ---- launch 4 (ncu capture slot): the pre GEMM ----
    gemm_mma_kernel<<<dim3(N_ / 128, 1), 256, SM_GEMM>>>(x, C_, 256, img_pre, 128,
                                                         pre_b, p_t0, (float*)0);

    // ---- remaining preps + BN(x0) ----
    for (int l = 0; l < 5; l++)
        prep_w_kernel<<<16, 256>>>(sf_W + (size_t)l * HID_ * HID_, HID_, 128,
                                   img_sf + (size_t)l * 32768);
    run_bn(p_t0, p_x0, bn0_g, bn0_b, p_stats, N_, 0);

    // ---- sort pixel-graph edges by src -> CSR ----
    zero_kernel<<<N_ / 256, 256>>>(p_hist, N_);
    hist_kernel<<<EM_ / 256, 256>>>(m_src, EM_, p_hist);
    scan_block_kernel<<<N_ / 1024, 1024>>>(p_hist, N_, p_peOff, p_aux);
    scan_aux_kernel<<<1, 1024>>>(p_aux, N_ / 1024);
    scan_add_kernel<<<N_ / 256, 256>>>(p_peOff, N_, p_aux, p_peCur, EM_);
    scatter_edge_kernel<<<EM_ / 256, 256>>>(m_src, m_dst, EM_, p_peCur, p_peDst);

    // ---- sort superpixel-graph edges by dst -> CSR ----
    zero_kernel<<<S_ / 256, 256>>>(p_hist, S_);
    hist_kernel<<<EA_ / 256, 256>>>(a_dst, EA_, p_hist);
    scan_block_kernel<<<S_ / 1024, 1024>>>(p_hist, S_, p_aOff, p_aux);
    scan_aux_kernel<<<1, 1024>>>(p_aux, S_ / 1024);
    scan_add_kernel<<<S_ / 256, 256>>>(p_aOff, S_, p_aux, p_aCur, EA_);
    scatter_aedge_kernel<<<EA_ / 256, 256>>>(a_dst, a_src, a_w, EA_, p_aCur, p_aSrc, p_aW);

    // ---- sort pixels by seg -> CSR ----
    zero_kernel<<<S_ / 256, 256>>>(p_hist, S_);
    hist_kernel<<<N_ / 256, 256>>>(seg, N_, p_hist);
    scan_block_kernel<<<S_ / 1024, 1024>>>(p_hist, S_, p_pOff, p_aux);
    scan_aux_kernel<<<1, 1024>>>(p_aux, S_ / 1024);
    scan_add_kernel<<<S_ / 256, 256>>>(p_pOff, S_, p_aux, p_pCur, N_);
    scatter_pix_kernel<<<N_ / 256, 256>>>(seg, N_, p_pCur, p_pSort);

    // ---- PF branch: 2 attention layers on pixel graph ----
    const float* pfin = p_x0;
    for (int l = 0; l < 2; l++) {
        gemm_mma_kernel<<<dim3(N_ / 128, 2), 256, SM_GEMM>>>(pfin, HID_, 128,
                                                             (l == 0) ? img_qv0 : img_qv1, 256,
                                                             p_biasQV + l * 256, p_Q, p_V);
        ln_kernel<<<N_ / 8, 256>>>(p_Q);
        attn_kernel<<<N_ / 8, 256>>>(p_Q, p_V, p_peOff, p_peDst, p_t0);
        run_bn(p_t0, p_pf, pf_g + l * HID_, pf_beta + l * HID_, p_stats, N_, 1);
        pfin = p_pf;
    }

    // ---- Hyperpixel branch: pool + 5 SF layers ----
    pool_kernel<<<S_ / 8, 256>>>(p_x0, p_pOff, p_pSort, p_hp);
    const float inv2g = 1.0f / 2.9f;
    for (int l = 0; l < 5; l++) {
        gemm_mma_kernel<<<dim3(S_ / 128, 1), 256, SM_GEMM>>>(p_hp, HID_, 128,
                                                             img_sf + (size_t)l * 32768, 128,
                                                             sf_b + l * HID_, p_h, (float*)0);
        prop_kernel<<<S_ / 8, 256>>>(p_h, p_aOff, p_aSrc, p_aW, (const float*)0, 1.0f, p_xs);
        const float* cur = p_hp;
        float* nxt = p_cA;
        for (int it = 0; it < 5; it++) {
            prop_kernel<<<S_ / 8, 256>>>(cur, p_aOff, p_aSrc, p_aW, p_xs, inv2g, nxt);
            cur = nxt;
            nxt = (cur == p_cA) ? p_cB : p_cA;
        }
        run_bn(cur, p_hp, sf_g + l * HID_, sf_beta + l * HID_, p_stats, S_, 1);
    }

    // ---- final fused output ----
    final_kernel<<<N_ / 8, 256>>>(p_pf, p_hp, seg, out_W, out_b, out);
}

// round 10
// speedup vs baseline: 1.2082x; 1.2082x over previous
#include <cuda_runtime.h>
#include <cuda_bf16.h>
#include <cstdint>
#include <cstddef>
#include <math.h>

#define N_  262144
#define C_  200
#define HID_ 128
#define S_  4096
#define EA_ 65536
#define EM_ 2097152
#define NC_ 16

// ---------------- device scratch ----------------
__device__ float g_x0[(size_t)N_ * HID_];
__device__ float g_t0[(size_t)N_ * HID_];
__device__ float g_pf[(size_t)N_ * HID_];
__device__ float g_Q [(size_t)N_ * HID_];
__device__ float g_V [(size_t)N_ * HID_];

__device__ float g_hp[S_ * HID_];
__device__ float g_h [S_ * HID_];
__device__ float g_xs[S_ * HID_];
__device__ float g_cA[S_ * HID_];
__device__ float g_cB[S_ * HID_];

__device__ int   g_hist[N_];
__device__ int   g_aux[1024];
__device__ int   g_peOff[N_ + 1];
__device__ int   g_peCur[N_];
__device__ int   g_peDst[EM_];
__device__ int   g_aOff[S_ + 1];
__device__ int   g_aCur[S_];
__device__ int   g_aSrc[EA_];
__device__ float g_aW [EA_];
__device__ int   g_pOff[S_ + 1];
__device__ int   g_pCur[S_];
__device__ int   g_pSort[N_];
__device__ float g_stats[256];

__device__ __align__(256) unsigned char g_Bimg[720896];
__device__ float g_biasQV[512];

// ---------------- split helpers ----------------
__device__ __forceinline__ void split4(float4 v, uint32_t& h01, uint32_t& h23,
                                       uint32_t& l01, uint32_t& l23) {
    __nv_bfloat16 h0 = __float2bfloat16(v.x), h1 = __float2bfloat16(v.y);
    __nv_bfloat16 h2 = __float2bfloat16(v.z), h3 = __float2bfloat16(v.w);
    __nv_bfloat16 l0 = __float2bfloat16(v.x - __bfloat162float(h0));
    __nv_bfloat16 l1 = __float2bfloat16(v.y - __bfloat162float(h1));
    __nv_bfloat16 l2 = __float2bfloat16(v.z - __bfloat162float(h2));
    __nv_bfloat16 l3 = __float2bfloat16(v.w - __bfloat162float(h3));
    h01 = ((uint32_t)__bfloat16_as_ushort(h1) << 16) | (uint32_t)__bfloat16_as_ushort(h0);
    h23 = ((uint32_t)__bfloat16_as_ushort(h3) << 16) | (uint32_t)__bfloat16_as_ushort(h2);
    l01 = ((uint32_t)__bfloat16_as_ushort(l1) << 16) | (uint32_t)__bfloat16_as_ushort(l0);
    l23 = ((uint32_t)__bfloat16_as_ushort(l3) << 16) | (uint32_t)__bfloat16_as_ushort(l2);
}

__device__ __forceinline__ void mma16816(float* c, const uint32_t* a, const uint32_t* b) {
    asm volatile(
        "mma.sync.aligned.m16n8k16.row.col.f32.bf16.bf16.f32 "
        "{%0,%1,%2,%3}, {%4,%5,%6,%7}, {%8,%9}, {%0,%1,%2,%3};"
        : "+f"(c[0]), "+f"(c[1]), "+f"(c[2]), "+f"(c[3])
        : "r"(a[0]), "r"(a[1]), "r"(a[2]), "r"(a[3]), "r"(b[0]), "r"(b[1]));
}

// ---------------- prep kernels ----------------
__global__ void prep_w_kernel(const float* __restrict__ W, int Kreal, int Kp,
                              __nv_bfloat16* __restrict__ img) {
    int idx = blockIdx.x * 256 + threadIdx.x;
    int kq = Kp >> 2;
    if (idx >= 128 * kq) return;
    int n = idx / kq;
    int k = (idx - n * kq) * 4;
    float4 v;
    v.x = (k + 0 < Kreal) ? W[(k + 0) * 128 + n] : 0.f;
    v.y = (k + 1 < Kreal) ? W[(k + 1) * 128 + n] : 0.f;
    v.z = (k + 2 < Kreal) ? W[(k + 2) * 128 + n] : 0.f;
    v.w = (k + 3 < Kreal) ? W[(k + 3) * 128 + n] : 0.f;
    uint32_t h01, h23, l01, l23;
    split4(v, h01, h23, l01, l23);
    *(uint2*)(img + (size_t)n * Kp + k)                    = make_uint2(h01, h23);
    *(uint2*)(img + (size_t)128 * Kp + (size_t)n * Kp + k) = make_uint2(l01, l23);
}

__global__ void prep_qv_kernel(const float* __restrict__ Wq, const float* __restrict__ Wv,
                               const float* __restrict__ bq, const float* __restrict__ bv,
                               __nv_bfloat16* __restrict__ img, float* __restrict__ biasOut) {
    int idx = blockIdx.x * 256 + threadIdx.x;
    if (idx >= 256 * 32) return;
    int n = idx >> 5;
    int k = (idx & 31) * 4;
    const float* W = (n < 128) ? Wq : Wv;
    int nn = (n < 128) ? n : n - 128;
    int h = nn >> 6, col = nn & 63;
    float4 v;
    v.x = W[((h * 128) + k + 0) * 64 + col];
    v.y = W[((h * 128) + k + 1) * 64 + col];
    v.z = W[((h * 128) + k + 2) * 64 + col];
    v.w = W[((h * 128) + k + 3) * 64 + col];
    uint32_t h01, h23, l01, l23;
    split4(v, h01, h23, l01, l23);
    *(uint2*)(img + (size_t)n * 128 + k)                     = make_uint2(h01, h23);
    *(uint2*)(img + (size_t)256 * 128 + (size_t)n * 128 + k) = make_uint2(l01, l23);
    if ((idx & 31) == 0) biasOut[n] = (n < 128) ? bq[h * 64 + col] : bv[h * 64 + col];
}

// ---------------- warp-MMA GEMM, double-buffered pipeline (resubmit of R9; infra failed) ----------------
#define LDA 72
#define STAGE_B (4 * 128 * LDA * 2)      // bytes per stage: Ah+Al+Bh+Bl, bf16
#define SM_GEMM (2 * STAGE_B + 512)
__global__ __launch_bounds__(256) void gemm_mma_kernel(
    const float* __restrict__ A, int Kreal, int Kp,
    const __nv_bfloat16* __restrict__ Bimg, int Nc,
    const float* __restrict__ bias,
    float* __restrict__ outA, float* __restrict__ outB) {
    extern __shared__ char smem[];
    float* bsm = (float*)(smem + 2 * STAGE_B);
    int tid = threadIdx.x;
    int lane = tid & 31, wid = tid >> 5;
    int wm = wid & 3, wn = wid >> 2;                   // 4 x 2 warps
    long rowBase = (long)blockIdx.x * 128;
    int nh = blockIdx.y;
    const __nv_bfloat16* BsrcH = Bimg + (size_t)(nh * 128) * Kp;
    const __nv_bfloat16* BsrcL = Bimg + (size_t)Nc * Kp + (size_t)(nh * 128) * Kp;
    if (tid < 128) bsm[tid] = bias[nh * 128 + tid];

    int nch = Kp >> 6;
    int aRow = tid >> 4;
    int aCol0 = (tid & 15) * 4;

    float acc[2][8][4];
#pragma unroll
    for (int t = 0; t < 2; t++)
#pragma unroll
        for (int j = 0; j < 8; j++)
#pragma unroll
            for (int q = 0; q < 4; q++) acc[t][j][q] = 0.f;

    float4 aPre[8];
    // ---- prologue: load A chunk 0 into regs, cp.async B chunk 0 into stage 0 ----
#pragma unroll
    for (int i = 0; i < 8; i++) {
        int row = aRow + i * 16;
        int k = aCol0;
        float4 v = make_float4(0.f, 0.f, 0.f, 0.f);
        if (k < Kreal) {
            const float* ap = A + (rowBase + row) * (long)Kreal + k;
            if (k + 3 < Kreal) v = *(const float4*)ap;
            else {
                v.x = ap[0];
                if (k + 1 < Kreal) v.y = ap[1];
                if (k + 2 < Kreal) v.z = ap[2];
            }
        }
        aPre[i] = v;
    }
    {
        char* st = smem;  // stage 0
        __nv_bfloat16* Bh = (__nv_bfloat16*)(st + 2 * 128 * LDA * 2);
        __nv_bfloat16* Bl = Bh + 128 * LDA;
#pragma unroll
        for (int i = 0; i < 8; i++) {
            int flat = tid + i * 256;
            int plane = flat >> 10;
            int r = (flat >> 3) & 127;
            int q = flat & 7;
            const __nv_bfloat16* src = (plane ? BsrcL : BsrcH) + (size_t)r * Kp + q * 8;
            __nv_bfloat16* dst = (plane ? Bl : Bh) + r * LDA + q * 8;
            uint32_t da = (uint32_t)__cvta_generic_to_shared(dst);
            asm volatile("cp.async.ca.shared.global [%0], [%1], 16;" :: "r"(da), "l"(src));
        }
        asm volatile("cp.async.commit_group;" ::: "memory");
    }

    for (int ch = 0; ch < nch; ch++) {
        int cur = ch & 1;
        char* st = smem + cur * STAGE_B;
        __nv_bfloat16* Ah = (__nv_bfloat16*)st;
        __nv_bfloat16* Al = Ah + 128 * LDA;
        __nv_bfloat16* Bh = Al + 128 * LDA;
        __nv_bfloat16* Bl = Bh + 128 * LDA;

        // convert prefetched A regs -> smem (stage cur)
#pragma unroll
        for (int i = 0; i < 8; i++) {
            int row = aRow + i * 16;
            uint32_t h01, h23, l01, l23;
            split4(aPre[i], h01, h23, l01, l23);
            *(uint2*)(Ah + row * LDA + aCol0) = make_uint2(h01, h23);
            *(uint2*)(Al + row * LDA + aCol0) = make_uint2(l01, l23);
        }
        // prefetch A chunk ch+1 into regs (LDG latency hidden by MMA below)
        if (ch + 1 < nch) {
#pragma unroll
            for (int i = 0; i < 8; i++) {
                int row = aRow + i * 16;
                int k = (ch + 1) * 64 + aCol0;
                float4 v = make_float4(0.f, 0.f, 0.f, 0.f);
                if (k < Kreal) {
                    const float* ap = A + (rowBase + row) * (long)Kreal + k;
                    if (k + 3 < Kreal) v = *(const float4*)ap;
                    else {
                        v.x = ap[0];
                        if (k + 1 < Kreal) v.y = ap[1];
                        if (k + 2 < Kreal) v.z = ap[2];
                    }
                }
                aPre[i] = v;
            }
        }
        asm volatile("cp.async.wait_group 0;" ::: "memory");
        __syncthreads();
        // issue B chunk ch+1 into other stage (overlaps MMA burst below)
        if (ch + 1 < nch) {
            char* st2 = smem + (1 - cur) * STAGE_B;
            __nv_bfloat16* Bh2 = (__nv_bfloat16*)(st2 + 2 * 128 * LDA * 2);
            __nv_bfloat16* Bl2 = Bh2 + 128 * LDA;
#pragma unroll
            for (int i = 0; i < 8; i++) {
                int flat = tid + i * 256;
                int plane = flat >> 10;
                int r = (flat >> 3) & 127;
                int q = flat & 7;
                const __nv_bfloat16* src = (plane ? BsrcL : BsrcH) + (size_t)r * Kp +
                                           (ch + 1) * 64 + q * 8;
                __nv_bfloat16* dst = (plane ? Bl2 : Bh2) + r * LDA + q * 8;
                uint32_t da = (uint32_t)__cvta_generic_to_shared(dst);
                asm volatile("cp.async.ca.shared.global [%0], [%1], 16;" :: "r"(da), "l"(src));
            }
            asm volatile("cp.async.commit_group;" ::: "memory");
        }

        // MMA burst on stage cur
#pragma unroll
        for (int ks = 0; ks < 4; ks++) {
            int kk = ks * 16;
            uint32_t ah[2][4], al[2][4];
#pragma unroll
            for (int t = 0; t < 2; t++) {
                int r0 = wm * 32 + t * 16 + (lane >> 2);
                int cA = kk + (lane & 3) * 2;
                ah[t][0] = *(const uint32_t*)(Ah + r0 * LDA + cA);
                ah[t][1] = *(const uint32_t*)(Ah + (r0 + 8) * LDA + cA);
                ah[t][2] = *(const uint32_t*)(Ah + r0 * LDA + cA + 8);
                ah[t][3] = *(const uint32_t*)(Ah + (r0 + 8) * LDA + cA + 8);
                al[t][0] = *(const uint32_t*)(Al + r0 * LDA + cA);
                al[t][1] = *(const uint32_t*)(Al + (r0 + 8) * LDA + cA);
                al[t][2] = *(const uint32_t*)(Al + r0 * LDA + cA + 8);
                al[t][3] = *(const uint32_t*)(Al + (r0 + 8) * LDA + cA + 8);
            }
            uint32_t bh[8][2], bl[8][2];
#pragma unroll
            for (int j = 0; j < 8; j++) {
                int cn = wn * 64 + j * 8 + (lane >> 2);
                int cB = kk + (lane & 3) * 2;
                bh[j][0] = *(const uint32_t*)(Bh + cn * LDA + cB);
                bh[j][1] = *(const uint32_t*)(Bh + cn * LDA + cB + 8);
                bl[j][0] = *(const uint32_t*)(Bl + cn * LDA + cB);
                bl[j][1] = *(const uint32_t*)(Bl + cn * LDA + cB + 8);
            }
#pragma unroll
            for (int t = 0; t < 2; t++)
#pragma unroll
                for (int j = 0; j < 8; j++) {
                    mma16816(acc[t][j], ah[t], bh[j]);
                    mma16816(acc[t][j], al[t], bh[j]);
                    mma16816(acc[t][j], ah[t], bl[j]);
                }
        }
        __syncthreads();
    }

    float* outP = (nh == 0) ? outA : outB;
#pragma unroll
    for (int t = 0; t < 2; t++) {
        long r0 = rowBase + wm * 32 + t * 16 + (lane >> 2);
#pragma unroll
        for (int j = 0; j < 8; j++) {
            int cloc = wn * 64 + j * 8 + (lane & 3) * 2;
            float2 v0 = make_float2(acc[t][j][0] + bsm[cloc], acc[t][j][1] + bsm[cloc + 1]);
            float2 v1 = make_float2(acc[t][j][2] + bsm[cloc], acc[t][j][3] + bsm[cloc + 1]);
            *(float2*)(outP + r0 * 128 + cloc)       = v0;
            *(float2*)(outP + (r0 + 8) * 128 + cloc) = v1;
        }
    }
}

// ---------------- utilities ----------------
__global__ void zero_kernel(int* p, int n) {
    int i = blockIdx.x * blockDim.x + threadIdx.x;
    if (i < n) p[i] = 0;
}
__global__ void zerof_kernel(float* p, int n) {
    int i = blockIdx.x * blockDim.x + threadIdx.x;
    if (i < n) p[i] = 0.f;
}

__global__ void hist_kernel(const int* __restrict__ keys, int n, int* __restrict__ hist) {
    int i = blockIdx.x * blockDim.x + threadIdx.x;
    if (i < n) atomicAdd(&hist[keys[i]], 1);
}

__global__ void scan_block_kernel(const int* __restrict__ in, int n,
                                  int* __restrict__ excl_out, int* __restrict__ bsum) {
    __shared__ int sh[1024];
    int tid = threadIdx.x;
    int idx = blockIdx.x * 1024 + tid;
    int v = (idx < n) ? in[idx] : 0;
    sh[tid] = v;
    __syncthreads();
    for (int off = 1; off < 1024; off <<= 1) {
        int t = (tid >= off) ? sh[tid - off] : 0;
        __syncthreads();
        sh[tid] += t;
        __syncthreads();
    }
    if (idx < n) excl_out[idx] = sh[tid] - v;
    if (tid == 1023) bsum[blockIdx.x] = sh[tid];
}

__global__ void scan_aux_kernel(int* aux, int nb) {
    __shared__ int sh[1024];
    int tid = threadIdx.x;
    int v = (tid < nb) ? aux[tid] : 0;
    sh[tid] = v;
    __syncthreads();
    for (int off = 1; off < 1024; off <<= 1) {
        int t = (tid >= off) ? sh[tid - off] : 0;
        __syncthreads();
        sh[tid] += t;
        __syncthreads();
    }
    if (tid < nb) aux[tid] = sh[tid] - v;
}

__global__ void scan_add_kernel(int* off, int n, const int* __restrict__ aux,
                                int* __restrict__ cursor, int total) {
    int idx = blockIdx.x * blockDim.x + threadIdx.x;
    if (idx < n) {
        int v = off[idx] + aux[idx >> 10];
        off[idx] = v;
        cursor[idx] = v;
    }
    if (idx == 0) off[n] = total;
}

__global__ void scatter_edge_kernel(const int* __restrict__ src, const int* __restrict__ dst,
                                    int n, int* __restrict__ cur, int* __restrict__ outDst) {
    int i = blockIdx.x * blockDim.x + threadIdx.x;
    if (i < n) {
        int p = atomicAdd(&cur[src[i]], 1);
        outDst[p] = dst[i];
    }
}

__global__ void scatter_aedge_kernel(const int* __restrict__ dstKey, const int* __restrict__ srcVal,
                                     const float* __restrict__ wVal, int n,
                                     int* __restrict__ cur, int* __restrict__ outSrc,
                                     float* __restrict__ outW) {
    int i = blockIdx.x * blockDim.x + threadIdx.x;
    if (i < n) {
        int p = atomicAdd(&cur[dstKey[i]], 1);
        outSrc[p] = srcVal[i];
        outW[p]   = wVal[i];
    }
}

__global__ void scatter_pix_kernel(const int* __restrict__ seg, int n,
                                   int* __restrict__ cur, int* __restrict__ outPix) {
    int i = blockIdx.x * blockDim.x + threadIdx.x;
    if (i < n) {
        int p = atomicAdd(&cur[seg[i]], 1);
        outPix[p] = i;
    }
}

// ---------------- BatchNorm ----------------
__global__ __launch_bounds__(256) void bnstats_kernel(const float* __restrict__ X, int M,
                                                      float* __restrict__ stats) {
    int lane = threadIdx.x & 31;
    int rs = threadIdx.x >> 5;
    float4 s = make_float4(0.f, 0.f, 0.f, 0.f);
    float4 q = make_float4(0.f, 0.f, 0.f, 0.f);
    for (long r = blockIdx.x * 8 + rs; r < M; r += (long)gridDim.x * 8) {
        float4 v = *(const float4*)(X + r * HID_ + lane * 4);
        s.x += v.x; s.y += v.y; s.z += v.z; s.w += v.w;
        q.x += v.x * v.x; q.y += v.y * v.y; q.z += v.z * v.z; q.w += v.w * v.w;
    }
    __shared__ float shs[8][HID_];
    __shared__ float shq[8][HID_];
    shs[rs][lane * 4 + 0] = s.x; shs[rs][lane * 4 + 1] = s.y;
    shs[rs][lane * 4 + 2] = s.z; shs[rs][lane * 4 + 3] = s.w;
    shq[rs][lane * 4 + 0] = q.x; shq[rs][lane * 4 + 1] = q.y;
    shq[rs][lane * 4 + 2] = q.z; shq[rs][lane * 4 + 3] = q.w;
    __syncthreads();
    if (threadIdx.x < HID_) {
        int c = threadIdx.x;
        float ss = 0.f, qq = 0.f;
#pragma unroll
        for (int r = 0; r < 8; r++) { ss += shs[r][c]; qq += shq[r][c]; }
        atomicAdd(&stats[c], ss);
        atomicAdd(&stats[HID_ + c], qq);
    }
}

__global__ void bnprep_kernel(float* stats, const float* __restrict__ g,
                              const float* __restrict__ b, float invM) {
    int c = threadIdx.x;
    float m = stats[c] * invM;
    float var = stats[HID_ + c] * invM - m * m;
    float w = rsqrtf(var + 1e-5f);
    float sc = w * g[c];
    stats[HID_ + c] = sc;
    stats[c] = b[c] - m * sc;
}

__global__ void bnapply_kernel(const float* __restrict__ X, float* __restrict__ Y,
                               const float* __restrict__ stats, long M, int lrelu) {
    long idx = (long)blockIdx.x * blockDim.x + threadIdx.x;
    long total = M * 32;
    if (idx >= total) return;
    int c4 = (int)(idx & 31);
    float4 v = *(const float4*)(X + idx * 4);
    float in[4] = {v.x, v.y, v.z, v.w};
    float o[4];
#pragma unroll
    for (int j = 0; j < 4; j++) {
        int c = c4 * 4 + j;
        float y = in[j] * stats[HID_ + c] + stats[c];
        if (lrelu) y = (y >= 0.f) ? y : 0.01f * y;
        o[j] = y;
    }
    *(float4*)(Y + idx * 4) = make_float4(o[0], o[1], o[2], o[3]);
}

// ---------------- LayerNorm per 64-wide head ----------------
__global__ __launch_bounds__(256) void ln_kernel(float* __restrict__ Q) {
    int wid = threadIdx.x >> 5, lane = threadIdx.x & 31;
    long row = (long)blockIdx.x * 8 + wid;
    float4 v = *(float4*)(Q + row * HID_ + lane * 4);
    float s = v.x + v.y + v.z + v.w;
    float q = v.x * v.x + v.y * v.y + v.z * v.z + v.w * v.w;
#pragma unroll
    for (int o = 8; o >= 1; o >>= 1) {
        s += __shfl_xor_sync(0xffffffffu, s, o);
        q += __shfl_xor_sync(0xffffffffu, q, o);
    }
    float m = s * (1.0f / 64.0f);
    float var = q * (1.0f / 64.0f) - m * m;
    float w = rsqrtf(var + 1e-5f);
    v.x = (v.x - m) * w; v.y = (v.y - m) * w;
    v.z = (v.z - m) * w; v.w = (v.w - m) * w;
    *(float4*)(Q + row * HID_ + lane * 4) = v;
}

// ---------------- fused per-src softmax attention ----------------
#define MAXE 64
__global__ __launch_bounds__(256) void attn_kernel(
    const float* __restrict__ Q, const float* __restrict__ V,
    const int* __restrict__ off, const int* __restrict__ dsts,
    float* __restrict__ out) {
    __shared__ float she[8][MAXE][2];
    int wid = threadIdx.x >> 5, lane = threadIdx.x & 31;
    int src = blockIdx.x * 8 + wid;
    int o0 = off[src], o1 = off[src + 1];
    int deg = o1 - o0;
    int half = lane >> 4;
    float4 qs = *(const float4*)(Q + (long)src * HID_ + lane * 4);
    float z = 0.f;
    bool cached = (deg <= MAXE);
    for (int i = 0; i < deg; i++) {
        int d = dsts[o0 + i];
        float4 qd = *(const float4*)(Q + (long)d * HID_ + lane * 4);
        float p = qs.x * qd.x + qs.y * qd.y + qs.z * qd.z + qs.w * qd.w;
        p += __shfl_xor_sync(0xffffffffu, p, 8);
        p += __shfl_xor_sync(0xffffffffu, p, 4);
        p += __shfl_xor_sync(0xffffffffu, p, 2);
        p += __shfl_xor_sync(0xffffffffu, p, 1);
        float e = __expf(p * (1.0f / HID_));
        z += e;
        if (cached && (lane & 15) == 0) she[wid][i][half] = e;
    }
    __syncwarp();
    float invz = (deg > 0) ? 1.0f / z : 0.f;
    float4 acc = make_float4(0.f, 0.f, 0.f, 0.f);
    for (int i = 0; i < deg; i++) {
        int d = dsts[o0 + i];
        float e;
        if (cached) {
            e = she[wid][i][half];
        } else {
            float4 qd = *(const float4*)(Q + (long)d * HID_ + lane * 4);
            float p = qs.x * qd.x + qs.y * qd.y + qs.z * qd.z + qs.w * qd.w;
            p += __shfl_xor_sync(0xffffffffu, p, 8);
            p += __shfl_xor_sync(0xffffffffu, p, 4);
            p += __shfl_xor_sync(0xffffffffu, p, 2);
            p += __shfl_xor_sync(0xffffffffu, p, 1);
            e = __expf(p * (1.0f / HID_));
        }
        float a = e * invz;
        float4 vd = *(const float4*)(V + (long)d * HID_ + lane * 4);
        acc.x += a * vd.x; acc.y += a * vd.y;
        acc.z += a * vd.z; acc.w += a * vd.w;
    }
    *(float4*)(out + (long)src * HID_ + lane * 4) = acc;
}

// ---------------- superpixel mean pooling ----------------
__global__ __launch_bounds__(256) void pool_kernel(const float* __restrict__ X,
                                                   const int* __restrict__ off,
                                                   const int* __restrict__ pix,
                                                   float* __restrict__ hp) {
    int wid = threadIdx.x >> 5, lane = threadIdx.x & 31;
    int s = blockIdx.x * 8 + wid;
    int o0 = off[s], o1 = off[s + 1];
    float4 acc = make_float4(0.f, 0.f, 0.f, 0.f);
    for (int i = o0; i < o1; i++) {
        int p = pix[i];
        float4 v = *(const float4*)(X + (long)p * HID_ + lane * 4);
        acc.x += v.x; acc.y += v.y; acc.z += v.z; acc.w += v.w;
    }
    int deg = o1 - o0;
    float inv = 1.0f / (float)(deg > 0 ? deg : 1);
    acc.x *= inv; acc.y *= inv; acc.z *= inv; acc.w *= inv;
    *(float4*)(hp + (long)s * HID_ + lane * 4) = acc;
}

// ---------------- weighted sparse prop (dst-CSR) ----------------
__global__ __launch_bounds__(256) void prop_kernel(const float* __restrict__ X,
                                                   const int* __restrict__ off,
                                                   const int* __restrict__ srcs,
                                                   const float* __restrict__ w,
                                                   const float* __restrict__ add, float scale,
                                                   float* __restrict__ out) {
    int wid = threadIdx.x >> 5, lane = threadIdx.x & 31;
    int d = blockIdx.x * 8 + wid;
    int o0 = off[d], o1 = off[d + 1];
    float4 acc = make_float4(0.f, 0.f, 0.f, 0.f);
    for (int i = o0; i < o1; i++) {
        int sN = srcs[i];
        float ww = w[i];
        float4 v = *(const float4*)(X + (long)sN * HID_ + lane * 4);
        acc.x += ww * v.x; acc.y += ww * v.y;
        acc.z += ww * v.z; acc.w += ww * v.w;
    }
    if (add) {
        float4 a = *(const float4*)(add + (long)d * HID_ + lane * 4);
        acc.x = (acc.x + a.x) * scale; acc.y = (acc.y + a.y) * scale;
        acc.z = (acc.z + a.z) * scale; acc.w = (acc.w + a.w) * scale;
    }
    *(float4*)(out + (long)d * HID_ + lane * 4) = acc;
}

// ---------------- final: softmax((pf + hp[seg]) @ W + b) ----------------
__global__ __launch_bounds__(256) void final_kernel(const float* __restrict__ PF,
                                                    const float* __restrict__ HP,
                                                    const int* __restrict__ seg,
                                                    const float* __restrict__ W,
                                                    const float* __restrict__ bias,
                                                    float* __restrict__ out) {
    __shared__ float Ws[HID_ * NC_];
    __shared__ float bs[NC_];
    for (int i = threadIdx.x; i < HID_ * NC_; i += 256) Ws[i] = W[i];
    if (threadIdx.x < NC_) bs[threadIdx.x] = bias[threadIdx.x];
    __syncthreads();
    int wid = threadIdx.x >> 5, lane = threadIdx.x & 31;
    long row = (long)blockIdx.x * 8 + wid;
    int sg = seg[row];
    float4 p4 = *(const float4*)(PF + row * HID_ + lane * 4);
    float4 h4 = *(const float4*)(HP + (long)sg * HID_ + lane * 4);
    float h[4] = {p4.x + h4.x, p4.y + h4.y, p4.z + h4.z, p4.w + h4.w};
    float l[NC_];
#pragma unroll
    for (int c = 0; c < NC_; c++) {
        l[c] = h[0] * Ws[(lane * 4 + 0) * NC_ + c] + h[1] * Ws[(lane * 4 + 1) * NC_ + c] +
               h[2] * Ws[(lane * 4 + 2) * NC_ + c] + h[3] * Ws[(lane * 4 + 3) * NC_ + c];
    }
#pragma unroll
    for (int o = 16; o >= 1; o >>= 1) {
#pragma unroll
        for (int c = 0; c < NC_; c++) l[c] += __shfl_xor_sync(0xffffffffu, l[c], o);
    }
    float mx = -1e30f;
#pragma unroll
    for (int c = 0; c < NC_; c++) {
        l[c] += bs[c];
        mx = fmaxf(mx, l[c]);
    }
    float sum = 0.f;
#pragma unroll
    for (int c = 0; c < NC_; c++) {
        l[c] = __expf(l[c] - mx);
        sum += l[c];
    }
    float inv = 1.0f / sum;
    if (lane < NC_) {
        float v = 0.f;
#pragma unroll
        for (int c = 0; c < NC_; c++)
            if (lane == c) v = l[c];
        out[row * NC_ + lane] = v * inv;
    }
}

// ---------------- host orchestration ----------------
static void run_bn(const float* X, float* Y, const float* g, const float* b,
                   float* stats, long M, int lrelu) {
    zerof_kernel<<<1, 256>>>(stats, 256);
    int nb = (M >= 100000) ? 1024 : 16;
    bnstats_kernel<<<nb, 256>>>(X, (int)M, stats);
    bnprep_kernel<<<1, 128>>>(stats, g, b, 1.0f / (float)M);
    long total = M * 32;
    bnapply_kernel<<<(int)((total + 255) / 256), 256>>>(X, Y, stats, M, lrelu);
}

extern "C" void kernel_launch(void* const* d_in, const int* in_sizes, int n_in,
                              void* d_out, int out_size) {
    const float* x      = (const float*)d_in[0];
    const int*   seg    = (const int*)d_in[1];
    const int*   a_src  = (const int*)d_in[2];
    const int*   a_dst  = (const int*)d_in[3];
    const float* a_w    = (const float*)d_in[4];
    const int*   m_src  = (const int*)d_in[5];
    const int*   m_dst  = (const int*)d_in[6];
    const float* pre_W  = (const float*)d_in[7];
    const float* pre_b  = (const float*)d_in[8];
    const float* bn0_g  = (const float*)d_in[9];
    const float* bn0_b  = (const float*)d_in[10];
    const float* sf_W   = (const float*)d_in[11];
    const float* sf_b   = (const float*)d_in[12];
    const float* sf_g   = (const float*)d_in[13];
    const float* sf_beta= (const float*)d_in[14];
    const float* pf_Wv  = (const float*)d_in[15];
    const float* pf_bv  = (const float*)d_in[16];
    const float* pf_Wq  = (const float*)d_in[17];
    const float* pf_bq  = (const float*)d_in[18];
    const float* pf_g   = (const float*)d_in[19];
    const float* pf_beta= (const float*)d_in[20];
    const float* out_W  = (const float*)d_in[21];
    const float* out_b  = (const float*)d_in[22];
    float* out = (float*)d_out;

    float *p_x0, *p_t0, *p_pf, *p_Q, *p_V, *p_hp, *p_h, *p_xs, *p_cA, *p_cB, *p_aW, *p_stats, *p_biasQV;
    int *p_hist, *p_aux, *p_peOff, *p_peCur, *p_peDst, *p_aOff, *p_aCur, *p_aSrc;
    int *p_pOff, *p_pCur, *p_pSort;
    unsigned char* p_img;
    cudaGetSymbolAddress((void**)&p_x0, g_x0);
    cudaGetSymbolAddress((void**)&p_t0, g_t0);
    cudaGetSymbolAddress((void**)&p_pf, g_pf);
    cudaGetSymbolAddress((void**)&p_Q,  g_Q);
    cudaGetSymbolAddress((void**)&p_V,  g_V);
    cudaGetSymbolAddress((void**)&p_hp, g_hp);
    cudaGetSymbolAddress((void**)&p_h,  g_h);
    cudaGetSymbolAddress((void**)&p_xs, g_xs);
    cudaGetSymbolAddress((void**)&p_cA, g_cA);
    cudaGetSymbolAddress((void**)&p_cB, g_cB);
    cudaGetSymbolAddress((void**)&p_aW, g_aW);
    cudaGetSymbolAddress((void**)&p_stats, g_stats);
    cudaGetSymbolAddress((void**)&p_hist, g_hist);
    cudaGetSymbolAddress((void**)&p_aux, g_aux);
    cudaGetSymbolAddress((void**)&p_peOff, g_peOff);
    cudaGetSymbolAddress((void**)&p_peCur, g_peCur);
    cudaGetSymbolAddress((void**)&p_peDst, g_peDst);
    cudaGetSymbolAddress((void**)&p_aOff, g_aOff);
    cudaGetSymbolAddress((void**)&p_aCur, g_aCur);
    cudaGetSymbolAddress((void**)&p_aSrc, g_aSrc);
    cudaGetSymbolAddress((void**)&p_pOff, g_pOff);
    cudaGetSymbolAddress((void**)&p_pCur, g_pCur);
    cudaGetSymbolAddress((void**)&p_pSort, g_pSort);
    cudaGetSymbolAddress((void**)&p_img, g_Bimg);
    cudaGetSymbolAddress((void**)&p_biasQV, g_biasQV);

    cudaFuncSetAttribute(gemm_mma_kernel, cudaFuncAttributeMaxDynamicSharedMemorySize, SM_GEMM);

    __nv_bfloat16* img_pre = (__nv_bfloat16*)p_img;                  // Kp=256, Nc=128
    __nv_bfloat16* img_qv0 = (__nv_bfloat16*)(p_img + 131072);       // Kp=128, Nc=256
    __nv_bfloat16* img_qv1 = (__nv_bfloat16*)(p_img + 262144);
    __nv_bfloat16* img_sf  = (__nv_bfloat16*)(p_img + 393216);       // Kp=128, Nc=128

    // ---- launches 1-3: prep images needed by the pre-GEMM ----
    prep_w_kernel<<<32, 256>>>(pre_W, C_, 256, img_pre);
    prep_qv_kernel<<<32, 256>>>(pf_Wq, pf_Wv, pf_bq, pf_bv, img_qv0, p_biasQV);
    prep_qv_kernel<<<32, 256>>>(pf_Wq + (size_t)2 * HID_ * 64, pf_Wv + (size_t)2 * HID_ * 64,
                                pf_bq + HID_, pf_bv + HID_, img_qv1, p_biasQV + 256);

    // ---- launch 4 (ncu capture slot): the pre GEMM ----
    gemm_mma_kernel<<<dim3(N_ / 128, 1), 256, SM_GEMM>>>(x, C_, 256, img_pre, 128,
                                                         pre_b, p_t0, (float*)0);

    // ---- remaining preps + BN(x0) ----
    for (int l = 0; l < 5; l++)
        prep_w_kernel<<<16, 256>>>(sf_W + (size_t)l * HID_ * HID_, HID_, 128,
                                   img_sf + (size_t)l * 32768);
    run_bn(p_t0, p_x0, bn0_g, bn0_b, p_stats, N_, 0);

    // ---- sort pixel-graph edges by src -> CSR ----
    zero_kernel<<<N_ / 256, 256>>>(p_hist, N_);
    hist_kernel<<<EM_ / 256, 256>>>(m_src, EM_, p_hist);
    scan_block_kernel<<<N_ / 1024, 1024>>>(p_hist, N_, p_peOff, p_aux);
    scan_aux_kernel<<<1, 1024>>>(p_aux, N_ / 1024);
    scan_add_kernel<<<N_ / 256, 256>>>(p_peOff, N_, p_aux, p_peCur, EM_);
    scatter_edge_kernel<<<EM_ / 256, 256>>>(m_src, m_dst, EM_, p_peCur, p_peDst);

    // ---- sort superpixel-graph edges by dst -> CSR ----
    zero_kernel<<<S_ / 256, 256>>>(p_hist, S_);
    hist_kernel<<<EA_ / 256, 256>>>(a_dst, EA_, p_hist);
    scan_block_kernel<<<S_ / 1024, 1024>>>(p_hist, S_, p_aOff, p_aux);
    scan_aux_kernel<<<1, 1024>>>(p_aux, S_ / 1024);
    scan_add_kernel<<<S_ / 256, 256>>>(p_aOff, S_, p_aux, p_aCur, EA_);
    scatter_aedge_kernel<<<EA_ / 256, 256>>>(a_dst, a_src, a_w, EA_, p_aCur, p_aSrc, p_aW);

    // ---- sort pixels by seg -> CSR ----
    zero_kernel<<<S_ / 256, 256>>>(p_hist, S_);
    hist_kernel<<<N_ / 256, 256>>>(seg, N_, p_hist);
    scan_block_kernel<<<S_ / 1024, 1024>>>(p_hist, S_, p_pOff, p_aux);
    scan_aux_kernel<<<1, 1024>>>(p_aux, S_ / 1024);
    scan_add_kernel<<<S_ / 256, 256>>>(p_pOff, S_, p_aux, p_pCur, N_);
    scatter_pix_kernel<<<N_ / 256, 256>>>(seg, N_, p_pCur, p_pSort);

    // ---- PF branch: 2 attention layers on pixel graph ----
    const float* pfin = p_x0;
    for (int l = 0; l < 2; l++) {
        gemm_mma_kernel<<<dim3(N_ / 128, 2), 256, SM_GEMM>>>(pfin, HID_, 128,
                                                             (l == 0) ? img_qv0 : img_qv1, 256,
                                                             p_biasQV + l * 256, p_Q, p_V);
        ln_kernel<<<N_ / 8, 256>>>(p_Q);
        attn_kernel<<<N_ / 8, 256>>>(p_Q, p_V, p_peOff, p_peDst, p_t0);
        run_bn(p_t0, p_pf, pf_g + l * HID_, pf_beta + l * HID_, p_stats, N_, 1);
        pfin = p_pf;
    }

    // ---- Hyperpixel branch: pool + 5 SF layers ----
    pool_kernel<<<S_ / 8, 256>>>(p_x0, p_pOff, p_pSort, p_hp);
    const float inv2g = 1.0f / 2.9f;
    for (int l = 0; l < 5; l++) {
        gemm_mma_kernel<<<dim3(S_ / 128, 1), 256, SM_GEMM>>>(p_hp, HID_, 128,
                                                             img_sf + (size_t)l * 32768, 128,
                                                             sf_b + l * HID_, p_h, (float*)0);
        prop_kernel<<<S_ / 8, 256>>>(p_h, p_aOff, p_aSrc, p_aW, (const float*)0, 1.0f, p_xs);
        const float* cur = p_hp;
        float* nxt = p_cA;
        for (int it = 0; it < 5; it++) {
            prop_kernel<<<S_ / 8, 256>>>(cur, p_aOff, p_aSrc, p_aW, p_xs, inv2g, nxt);
            cur = nxt;
            nxt = (cur == p_cA) ? p_cB : p_cA;
        }
        run_bn(cur, p_hp, sf_g + l * HID_, sf_beta + l * HID_, p_stats, S_, 1);
    }

    // ---- final fused output ----
    final_kernel<<<N_ / 8, 256>>>(p_pf, p_hp, seg, out_W, out_b, out);
}

// round 11
// speedup vs baseline: 1.3284x; 1.0995x over previous
#include <cuda_runtime.h>
#include <cuda_bf16.h>
#include <cuda_fp16.h>
#include <cstdint>
#include <cstddef>
#include <math.h>

#define N_  262144
#define C_  200
#define HID_ 128
#define S_  4096
#define EA_ 65536
#define EM_ 2097152
#define NC_ 16

// ---------------- device scratch ----------------
__device__ float g_x0[(size_t)N_ * HID_];
__device__ float g_t0[(size_t)N_ * HID_];
__device__ float g_pf[(size_t)N_ * HID_];
__device__ float g_Q [(size_t)N_ * HID_];
__device__ float g_V [(size_t)N_ * HID_];
__device__ __half g_Qh[(size_t)N_ * HID_];
__device__ __half g_Vh[(size_t)N_ * HID_];

__device__ float g_hp[S_ * HID_];
__device__ float g_h [S_ * HID_];
__device__ float g_xs[S_ * HID_];
__device__ float g_cA[S_ * HID_];
__device__ float g_cB[S_ * HID_];

__device__ int   g_hist[N_];
__device__ int   g_aux[1024];
__device__ int   g_peOff[N_ + 1];
__device__ int   g_peCur[N_];
__device__ int   g_peDst[EM_];
__device__ int   g_aOff[S_ + 1];
__device__ int   g_aCur[S_];
__device__ int   g_aSrc[EA_];
__device__ float g_aW [EA_];
__device__ int   g_pOff[S_ + 1];
__device__ int   g_pCur[S_];
__device__ int   g_pSort[N_];
__device__ float g_stats[256];

__device__ __align__(256) unsigned char g_Bimg[720896];
__device__ float g_biasQV[512];

// ---------------- split helpers ----------------
__device__ __forceinline__ void split4(float4 v, uint32_t& h01, uint32_t& h23,
                                       uint32_t& l01, uint32_t& l23) {
    __nv_bfloat16 h0 = __float2bfloat16(v.x), h1 = __float2bfloat16(v.y);
    __nv_bfloat16 h2 = __float2bfloat16(v.z), h3 = __float2bfloat16(v.w);
    __nv_bfloat16 l0 = __float2bfloat16(v.x - __bfloat162float(h0));
    __nv_bfloat16 l1 = __float2bfloat16(v.y - __bfloat162float(h1));
    __nv_bfloat16 l2 = __float2bfloat16(v.z - __bfloat162float(h2));
    __nv_bfloat16 l3 = __float2bfloat16(v.w - __bfloat162float(h3));
    h01 = ((uint32_t)__bfloat16_as_ushort(h1) << 16) | (uint32_t)__bfloat16_as_ushort(h0);
    h23 = ((uint32_t)__bfloat16_as_ushort(h3) << 16) | (uint32_t)__bfloat16_as_ushort(h2);
    l01 = ((uint32_t)__bfloat16_as_ushort(l1) << 16) | (uint32_t)__bfloat16_as_ushort(l0);
    l23 = ((uint32_t)__bfloat16_as_ushort(l3) << 16) | (uint32_t)__bfloat16_as_ushort(l2);
}

__device__ __forceinline__ void mma16816(float* c, const uint32_t* a, const uint32_t* b) {
    asm volatile(
        "mma.sync.aligned.m16n8k16.row.col.f32.bf16.bf16.f32 "
        "{%0,%1,%2,%3}, {%4,%5,%6,%7}, {%8,%9}, {%0,%1,%2,%3};"
        : "+f"(c[0]), "+f"(c[1]), "+f"(c[2]), "+f"(c[3])
        : "r"(a[0]), "r"(a[1]), "r"(a[2]), "r"(a[3]), "r"(b[0]), "r"(b[1]));
}

// ---------------- prep kernels ----------------
__global__ void prep_w_kernel(const float* __restrict__ W, int Kreal, int Kp,
                              __nv_bfloat16* __restrict__ img) {
    int idx = blockIdx.x * 256 + threadIdx.x;
    int kq = Kp >> 2;
    if (idx >= 128 * kq) return;
    int n = idx / kq;
    int k = (idx - n * kq) * 4;
    float4 v;
    v.x = (k + 0 < Kreal) ? W[(k + 0) * 128 + n] : 0.f;
    v.y = (k + 1 < Kreal) ? W[(k + 1) * 128 + n] : 0.f;
    v.z = (k + 2 < Kreal) ? W[(k + 2) * 128 + n] : 0.f;
    v.w = (k + 3 < Kreal) ? W[(k + 3) * 128 + n] : 0.f;
    uint32_t h01, h23, l01, l23;
    split4(v, h01, h23, l01, l23);
    *(uint2*)(img + (size_t)n * Kp + k)                    = make_uint2(h01, h23);
    *(uint2*)(img + (size_t)128 * Kp + (size_t)n * Kp + k) = make_uint2(l01, l23);
}

__global__ void prep_qv_kernel(const float* __restrict__ Wq, const float* __restrict__ Wv,
                               const float* __restrict__ bq, const float* __restrict__ bv,
                               __nv_bfloat16* __restrict__ img, float* __restrict__ biasOut) {
    int idx = blockIdx.x * 256 + threadIdx.x;
    if (idx >= 256 * 32) return;
    int n = idx >> 5;
    int k = (idx & 31) * 4;
    const float* W = (n < 128) ? Wq : Wv;
    int nn = (n < 128) ? n : n - 128;
    int h = nn >> 6, col = nn & 63;
    float4 v;
    v.x = W[((h * 128) + k + 0) * 64 + col];
    v.y = W[((h * 128) + k + 1) * 64 + col];
    v.z = W[((h * 128) + k + 2) * 64 + col];
    v.w = W[((h * 128) + k + 3) * 64 + col];
    uint32_t h01, h23, l01, l23;
    split4(v, h01, h23, l01, l23);
    *(uint2*)(img + (size_t)n * 128 + k)                     = make_uint2(h01, h23);
    *(uint2*)(img + (size_t)256 * 128 + (size_t)n * 128 + k) = make_uint2(l01, l23);
    if ((idx & 31) == 0) biasOut[n] = (n < 128) ? bq[h * 64 + col] : bv[h * 64 + col];
}

// ---------------- warp-MMA GEMM, double-buffered pipeline ----------------
#define LDA 72
#define STAGE_B (4 * 128 * LDA * 2)      // bytes per stage: Ah+Al+Bh+Bl, bf16
#define SM_GEMM (2 * STAGE_B + 512)
__global__ __launch_bounds__(256) void gemm_mma_kernel(
    const float* __restrict__ A, int Kreal, int Kp,
    const __nv_bfloat16* __restrict__ Bimg, int Nc,
    const float* __restrict__ bias,
    float* __restrict__ outA, float* __restrict__ outB) {
    extern __shared__ char smem[];
    float* bsm = (float*)(smem + 2 * STAGE_B);
    int tid = threadIdx.x;
    int lane = tid & 31, wid = tid >> 5;
    int wm = wid & 3, wn = wid >> 2;                   // 4 x 2 warps
    long rowBase = (long)blockIdx.x * 128;
    int nh = blockIdx.y;
    const __nv_bfloat16* BsrcH = Bimg + (size_t)(nh * 128) * Kp;
    const __nv_bfloat16* BsrcL = Bimg + (size_t)Nc * Kp + (size_t)(nh * 128) * Kp;
    if (tid < 128) bsm[tid] = bias[nh * 128 + tid];

    int nch = Kp >> 6;
    int aRow = tid >> 4;
    int aCol0 = (tid & 15) * 4;

    float acc[2][8][4];
#pragma unroll
    for (int t = 0; t < 2; t++)
#pragma unroll
        for (int j = 0; j < 8; j++)
#pragma unroll
            for (int q = 0; q < 4; q++) acc[t][j][q] = 0.f;

    float4 aPre[8];
#pragma unroll
    for (int i = 0; i < 8; i++) {
        int row = aRow + i * 16;
        int k = aCol0;
        float4 v = make_float4(0.f, 0.f, 0.f, 0.f);
        if (k < Kreal) {
            const float* ap = A + (rowBase + row) * (long)Kreal + k;
            if (k + 3 < Kreal) v = *(const float4*)ap;
            else {
                v.x = ap[0];
                if (k + 1 < Kreal) v.y = ap[1];
                if (k + 2 < Kreal) v.z = ap[2];
            }
        }
        aPre[i] = v;
    }
    {
        char* st = smem;  // stage 0
        __nv_bfloat16* Bh = (__nv_bfloat16*)(st + 2 * 128 * LDA * 2);
        __nv_bfloat16* Bl = Bh + 128 * LDA;
#pragma unroll
        for (int i = 0; i < 8; i++) {
            int flat = tid + i * 256;
            int plane = flat >> 10;
            int r = (flat >> 3) & 127;
            int q = flat & 7;
            const __nv_bfloat16* src = (plane ? BsrcL : BsrcH) + (size_t)r * Kp + q * 8;
            __nv_bfloat16* dst = (plane ? Bl : Bh) + r * LDA + q * 8;
            uint32_t da = (uint32_t)__cvta_generic_to_shared(dst);
            asm volatile("cp.async.ca.shared.global [%0], [%1], 16;" :: "r"(da), "l"(src));
        }
        asm volatile("cp.async.commit_group;" ::: "memory");
    }

    for (int ch = 0; ch < nch; ch++) {
        int cur = ch & 1;
        char* st = smem + cur * STAGE_B;
        __nv_bfloat16* Ah = (__nv_bfloat16*)st;
        __nv_bfloat16* Al = Ah + 128 * LDA;
        __nv_bfloat16* Bh = Al + 128 * LDA;
        __nv_bfloat16* Bl = Bh + 128 * LDA;

#pragma unroll
        for (int i = 0; i < 8; i++) {
            int row = aRow + i * 16;
            uint32_t h01, h23, l01, l23;
            split4(aPre[i], h01, h23, l01, l23);
            *(uint2*)(Ah + row * LDA + aCol0) = make_uint2(h01, h23);
            *(uint2*)(Al + row * LDA + aCol0) = make_uint2(l01, l23);
        }
        if (ch + 1 < nch) {
#pragma unroll
            for (int i = 0; i < 8; i++) {
                int row = aRow + i * 16;
                int k = (ch + 1) * 64 + aCol0;
                float4 v = make_float4(0.f, 0.f, 0.f, 0.f);
                if (k < Kreal) {
                    const float* ap = A + (rowBase + row) * (long)Kreal + k;
                    if (k + 3 < Kreal) v = *(const float4*)ap;
                    else {
                        v.x = ap[0];
                        if (k + 1 < Kreal) v.y = ap[1];
                        if (k + 2 < Kreal) v.z = ap[2];
                    }
                }
                aPre[i] = v;
            }
        }
        asm volatile("cp.async.wait_group 0;" ::: "memory");
        __syncthreads();
        if (ch + 1 < nch) {
            char* st2 = smem + (1 - cur) * STAGE_B;
            __nv_bfloat16* Bh2 = (__nv_bfloat16*)(st2 + 2 * 128 * LDA * 2);
            __nv_bfloat16* Bl2 = Bh2 + 128 * LDA;
#pragma unroll
            for (int i = 0; i < 8; i++) {
                int flat = tid + i * 256;
                int plane = flat >> 10;
                int r = (flat >> 3) & 127;
                int q = flat & 7;
                const __nv_bfloat16* src = (plane ? BsrcL : BsrcH) + (size_t)r * Kp +
                                           (ch + 1) * 64 + q * 8;
                __nv_bfloat16* dst = (plane ? Bl2 : Bh2) + r * LDA + q * 8;
                uint32_t da = (uint32_t)__cvta_generic_to_shared(dst);
                asm volatile("cp.async.ca.shared.global [%0], [%1], 16;" :: "r"(da), "l"(src));
            }
            asm volatile("cp.async.commit_group;" ::: "memory");
        }

#pragma unroll
        for (int ks = 0; ks < 4; ks++) {
            int kk = ks * 16;
            uint32_t ah[2][4], al[2][4];
#pragma unroll
            for (int t = 0; t < 2; t++) {
                int r0 = wm * 32 + t * 16 + (lane >> 2);
                int cA = kk + (lane & 3) * 2;
                ah[t][0] = *(const uint32_t*)(Ah + r0 * LDA + cA);
                ah[t][1] = *(const uint32_t*)(Ah + (r0 + 8) * LDA + cA);
                ah[t][2] = *(const uint32_t*)(Ah + r0 * LDA + cA + 8);
                ah[t][3] = *(const uint32_t*)(Ah + (r0 + 8) * LDA + cA + 8);
                al[t][0] = *(const uint32_t*)(Al + r0 * LDA + cA);
                al[t][1] = *(const uint32_t*)(Al + (r0 + 8) * LDA + cA);
                al[t][2] = *(const uint32_t*)(Al + r0 * LDA + cA + 8);
                al[t][3] = *(const uint32_t*)(Al + (r0 + 8) * LDA + cA + 8);
            }
            uint32_t bh[8][2], bl[8][2];
#pragma unroll
            for (int j = 0; j < 8; j++) {
                int cn = wn * 64 + j * 8 + (lane >> 2);
                int cB = kk + (lane & 3) * 2;
                bh[j][0] = *(const uint32_t*)(Bh + cn * LDA + cB);
                bh[j][1] = *(const uint32_t*)(Bh + cn * LDA + cB + 8);
                bl[j][0] = *(const uint32_t*)(Bl + cn * LDA + cB);
                bl[j][1] = *(const uint32_t*)(Bl + cn * LDA + cB + 8);
            }
#pragma unroll
            for (int t = 0; t < 2; t++)
#pragma unroll
                for (int j = 0; j < 8; j++) {
                    mma16816(acc[t][j], ah[t], bh[j]);
                    mma16816(acc[t][j], al[t], bh[j]);
                    mma16816(acc[t][j], ah[t], bl[j]);
                }
        }
        __syncthreads();
    }

    float* outP = (nh == 0) ? outA : outB;
#pragma unroll
    for (int t = 0; t < 2; t++) {
        long r0 = rowBase + wm * 32 + t * 16 + (lane >> 2);
#pragma unroll
        for (int j = 0; j < 8; j++) {
            int cloc = wn * 64 + j * 8 + (lane & 3) * 2;
            float2 v0 = make_float2(acc[t][j][0] + bsm[cloc], acc[t][j][1] + bsm[cloc + 1]);
            float2 v1 = make_float2(acc[t][j][2] + bsm[cloc], acc[t][j][3] + bsm[cloc + 1]);
            *(float2*)(outP + r0 * 128 + cloc)       = v0;
            *(float2*)(outP + (r0 + 8) * 128 + cloc) = v1;
        }
    }
}

// ---------------- utilities ----------------
__global__ void zero_kernel(int* p, int n) {
    int i = blockIdx.x * blockDim.x + threadIdx.x;
    if (i < n) p[i] = 0;
}
__global__ void zerof_kernel(float* p, int n) {
    int i = blockIdx.x * blockDim.x + threadIdx.x;
    if (i < n) p[i] = 0.f;
}

__global__ void hist_kernel(const int* __restrict__ keys, int n, int* __restrict__ hist) {
    int i = blockIdx.x * blockDim.x + threadIdx.x;
    if (i < n) atomicAdd(&hist[keys[i]], 1);
}

__global__ void scan_block_kernel(const int* __restrict__ in, int n,
                                  int* __restrict__ excl_out, int* __restrict__ bsum) {
    __shared__ int sh[1024];
    int tid = threadIdx.x;
    int idx = blockIdx.x * 1024 + tid;
    int v = (idx < n) ? in[idx] : 0;
    sh[tid] = v;
    __syncthreads();
    for (int off = 1; off < 1024; off <<= 1) {
        int t = (tid >= off) ? sh[tid - off] : 0;
        __syncthreads();
        sh[tid] += t;
        __syncthreads();
    }
    if (idx < n) excl_out[idx] = sh[tid] - v;
    if (tid == 1023) bsum[blockIdx.x] = sh[tid];
}

__global__ void scan_aux_kernel(int* aux, int nb) {
    __shared__ int sh[1024];
    int tid = threadIdx.x;
    int v = (tid < nb) ? aux[tid] : 0;
    sh[tid] = v;
    __syncthreads();
    for (int off = 1; off < 1024; off <<= 1) {
        int t = (tid >= off) ? sh[tid - off] : 0;
        __syncthreads();
        sh[tid] += t;
        __syncthreads();
    }
    if (tid < nb) aux[tid] = sh[tid] - v;
}

__global__ void scan_add_kernel(int* off, int n, const int* __restrict__ aux,
                                int* __restrict__ cursor, int total) {
    int idx = blockIdx.x * blockDim.x + threadIdx.x;
    if (idx < n) {
        int v = off[idx] + aux[idx >> 10];
        off[idx] = v;
        cursor[idx] = v;
    }
    if (idx == 0) off[n] = total;
}

__global__ void scatter_edge_kernel(const int* __restrict__ src, const int* __restrict__ dst,
                                    int n, int* __restrict__ cur, int* __restrict__ outDst) {
    int i = blockIdx.x * blockDim.x + threadIdx.x;
    if (i < n) {
        int p = atomicAdd(&cur[src[i]], 1);
        outDst[p] = dst[i];
    }
}

__global__ void scatter_aedge_kernel(const int* __restrict__ dstKey, const int* __restrict__ srcVal,
                                     const float* __restrict__ wVal, int n,
                                     int* __restrict__ cur, int* __restrict__ outSrc,
                                     float* __restrict__ outW) {
    int i = blockIdx.x * blockDim.x + threadIdx.x;
    if (i < n) {
        int p = atomicAdd(&cur[dstKey[i]], 1);
        outSrc[p] = srcVal[i];
        outW[p]   = wVal[i];
    }
}

__global__ void scatter_pix_kernel(const int* __restrict__ seg, int n,
                                   int* __restrict__ cur, int* __restrict__ outPix) {
    int i = blockIdx.x * blockDim.x + threadIdx.x;
    if (i < n) {
        int p = atomicAdd(&cur[seg[i]], 1);
        outPix[p] = i;
    }
}

// ---------------- BatchNorm ----------------
__global__ __launch_bounds__(256) void bnstats_kernel(const float* __restrict__ X, int M,
                                                      float* __restrict__ stats) {
    int lane = threadIdx.x & 31;
    int rs = threadIdx.x >> 5;
    float4 s = make_float4(0.f, 0.f, 0.f, 0.f);
    float4 q = make_float4(0.f, 0.f, 0.f, 0.f);
    for (long r = blockIdx.x * 8 + rs; r < M; r += (long)gridDim.x * 8) {
        float4 v = *(const float4*)(X + r * HID_ + lane * 4);
        s.x += v.x; s.y += v.y; s.z += v.z; s.w += v.w;
        q.x += v.x * v.x; q.y += v.y * v.y; q.z += v.z * v.z; q.w += v.w * v.w;
    }
    __shared__ float shs[8][HID_];
    __shared__ float shq[8][HID_];
    shs[rs][lane * 4 + 0] = s.x; shs[rs][lane * 4 + 1] = s.y;
    shs[rs][lane * 4 + 2] = s.z; shs[rs][lane * 4 + 3] = s.w;
    shq[rs][lane * 4 + 0] = q.x; shq[rs][lane * 4 + 1] = q.y;
    shq[rs][lane * 4 + 2] = q.z; shq[rs][lane * 4 + 3] = q.w;
    __syncthreads();
    if (threadIdx.x < HID_) {
        int c = threadIdx.x;
        float ss = 0.f, qq = 0.f;
#pragma unroll
        for (int r = 0; r < 8; r++) { ss += shs[r][c]; qq += shq[r][c]; }
        atomicAdd(&stats[c], ss);
        atomicAdd(&stats[HID_ + c], qq);
    }
}

__global__ void bnprep_kernel(float* stats, const float* __restrict__ g,
                              const float* __restrict__ b, float invM) {
    int c = threadIdx.x;
    float m = stats[c] * invM;
    float var = stats[HID_ + c] * invM - m * m;
    float w = rsqrtf(var + 1e-5f);
    float sc = w * g[c];
    stats[HID_ + c] = sc;
    stats[c] = b[c] - m * sc;
}

__global__ void bnapply_kernel(const float* __restrict__ X, float* __restrict__ Y,
                               const float* __restrict__ stats, long M, int lrelu) {
    long idx = (long)blockIdx.x * blockDim.x + threadIdx.x;
    long total = M * 32;
    if (idx >= total) return;
    int c4 = (int)(idx & 31);
    float4 v = *(const float4*)(X + idx * 4);
    float in[4] = {v.x, v.y, v.z, v.w};
    float o[4];
#pragma unroll
    for (int j = 0; j < 4; j++) {
        int c = c4 * 4 + j;
        float y = in[j] * stats[HID_ + c] + stats[c];
        if (lrelu) y = (y >= 0.f) ? y : 0.01f * y;
        o[j] = y;
    }
    *(float4*)(Y + idx * 4) = make_float4(o[0], o[1], o[2], o[3]);
}

// ---------------- LayerNorm per 64-wide head; outputs half ----------------
__global__ __launch_bounds__(256) void ln_kernel(const float* __restrict__ Q,
                                                 __half* __restrict__ Qh) {
    int wid = threadIdx.x >> 5, lane = threadIdx.x & 31;
    long row = (long)blockIdx.x * 8 + wid;
    float4 v = *(const float4*)(Q + row * HID_ + lane * 4);
    float s = v.x + v.y + v.z + v.w;
    float q = v.x * v.x + v.y * v.y + v.z * v.z + v.w * v.w;
#pragma unroll
    for (int o = 8; o >= 1; o >>= 1) {
        s += __shfl_xor_sync(0xffffffffu, s, o);
        q += __shfl_xor_sync(0xffffffffu, q, o);
    }
    float m = s * (1.0f / 64.0f);
    float var = q * (1.0f / 64.0f) - m * m;
    float w = rsqrtf(var + 1e-5f);
    __half2 a = __floats2half2_rn((v.x - m) * w, (v.y - m) * w);
    __half2 b = __floats2half2_rn((v.z - m) * w, (v.w - m) * w);
    uint2 o2;
    o2.x = *(uint32_t*)&a;
    o2.y = *(uint32_t*)&b;
    *(uint2*)(Qh + row * HID_ + lane * 4) = o2;
}

// ---------------- float -> half conversion ----------------
__global__ void convh_kernel(const float* __restrict__ X, __half* __restrict__ Y, long n4) {
    long idx = (long)blockIdx.x * blockDim.x + threadIdx.x;
    if (idx >= n4) return;
    float4 v = *(const float4*)(X + idx * 4);
    __half2 a = __floats2half2_rn(v.x, v.y);
    __half2 b = __floats2half2_rn(v.z, v.w);
    uint2 o2;
    o2.x = *(uint32_t*)&a;
    o2.y = *(uint32_t*)&b;
    *(uint2*)(Y + idx * 4) = o2;
}

// ---------------- fused per-src softmax attention (half Q/V) ----------------
#define MAXE 64
__global__ __launch_bounds__(256) void attn_kernel(
    const __half* __restrict__ Q, const __half* __restrict__ V,
    const int* __restrict__ off, const int* __restrict__ dsts,
    float* __restrict__ out) {
    __shared__ float she[8][MAXE][2];
    int wid = threadIdx.x >> 5, lane = threadIdx.x & 31;
    int src = blockIdx.x * 8 + wid;
    int o0 = off[src], o1 = off[src + 1];
    int deg = o1 - o0;
    int half_ = lane >> 4;
    uint2 qr = *(const uint2*)(Q + (long)src * HID_ + lane * 4);
    __half2 qsa = *(__half2*)&qr.x;
    __half2 qsb = *(__half2*)&qr.y;
    float q0 = __half2float(__low2half(qsa)),  q1 = __half2float(__high2half(qsa));
    float q2 = __half2float(__low2half(qsb)),  q3 = __half2float(__high2half(qsb));
    float z = 0.f;
    bool cached = (deg <= MAXE);
    for (int i = 0; i < deg; i++) {
        int d = dsts[o0 + i];
        uint2 dr = *(const uint2*)(Q + (long)d * HID_ + lane * 4);
        __half2 da = *(__half2*)&dr.x;
        __half2 db = *(__half2*)&dr.y;
        float p = q0 * __half2float(__low2half(da)) + q1 * __half2float(__high2half(da)) +
                  q2 * __half2float(__low2half(db)) + q3 * __half2float(__high2half(db));
        p += __shfl_xor_sync(0xffffffffu, p, 8);
        p += __shfl_xor_sync(0xffffffffu, p, 4);
        p += __shfl_xor_sync(0xffffffffu, p, 2);
        p += __shfl_xor_sync(0xffffffffu, p, 1);
        float e = __expf(p * (1.0f / HID_));
        z += e;
        if (cached && (lane & 15) == 0) she[wid][i][half_] = e;
    }
    __syncwarp();
    float invz = (deg > 0) ? 1.0f / z : 0.f;
    float4 acc = make_float4(0.f, 0.f, 0.f, 0.f);
    for (int i = 0; i < deg; i++) {
        int d = dsts[o0 + i];
        float e;
        if (cached) {
            e = she[wid][i][half_];
        } else {
            uint2 dr = *(const uint2*)(Q + (long)d * HID_ + lane * 4);
            __half2 da = *(__half2*)&dr.x;
            __half2 db = *(__half2*)&dr.y;
            float p = q0 * __half2float(__low2half(da)) + q1 * __half2float(__high2half(da)) +
                      q2 * __half2float(__low2half(db)) + q3 * __half2float(__high2half(db));
            p += __shfl_xor_sync(0xffffffffu, p, 8);
            p += __shfl_xor_sync(0xffffffffu, p, 4);
            p += __shfl_xor_sync(0xffffffffu, p, 2);
            p += __shfl_xor_sync(0xffffffffu, p, 1);
            e = __expf(p * (1.0f / HID_));
        }
        float a = e * invz;
        uint2 vr = *(const uint2*)(V + (long)d * HID_ + lane * 4);
        __half2 va = *(__half2*)&vr.x;
        __half2 vb = *(__half2*)&vr.y;
        acc.x += a * __half2float(__low2half(va));
        acc.y += a * __half2float(__high2half(va));
        acc.z += a * __half2float(__low2half(vb));
        acc.w += a * __half2float(__high2half(vb));
    }
    *(float4*)(out + (long)src * HID_ + lane * 4) = acc;
}

// ---------------- superpixel mean pooling ----------------
__global__ __launch_bounds__(256) void pool_kernel(const float* __restrict__ X,
                                                   const int* __restrict__ off,
                                                   const int* __restrict__ pix,
                                                   float* __restrict__ hp) {
    int wid = threadIdx.x >> 5, lane = threadIdx.x & 31;
    int s = blockIdx.x * 8 + wid;
    int o0 = off[s], o1 = off[s + 1];
    float4 acc = make_float4(0.f, 0.f, 0.f, 0.f);
    for (int i = o0; i < o1; i++) {
        int p = pix[i];
        float4 v = *(const float4*)(X + (long)p * HID_ + lane * 4);
        acc.x += v.x; acc.y += v.y; acc.z += v.z; acc.w += v.w;
    }
    int deg = o1 - o0;
    float inv = 1.0f / (float)(deg > 0 ? deg : 1);
    acc.x *= inv; acc.y *= inv; acc.z *= inv; acc.w *= inv;
    *(float4*)(hp + (long)s * HID_ + lane * 4) = acc;
}

// ---------------- weighted sparse prop (dst-CSR) ----------------
__global__ __launch_bounds__(256) void prop_kernel(const float* __restrict__ X,
                                                   const int* __restrict__ off,
                                                   const int* __restrict__ srcs,
                                                   const float* __restrict__ w,
                                                   const float* __restrict__ add, float scale,
                                                   float* __restrict__ out) {
    int wid = threadIdx.x >> 5, lane = threadIdx.x & 31;
    int d = blockIdx.x * 8 + wid;
    int o0 = off[d], o1 = off[d + 1];
    float4 acc = make_float4(0.f, 0.f, 0.f, 0.f);
    for (int i = o0; i < o1; i++) {
        int sN = srcs[i];
        float ww = w[i];
        float4 v = *(const float4*)(X + (long)sN * HID_ + lane * 4);
        acc.x += ww * v.x; acc.y += ww * v.y;
        acc.z += ww * v.z; acc.w += ww * v.w;
    }
    if (add) {
        float4 a = *(const float4*)(add + (long)d * HID_ + lane * 4);
        acc.x = (acc.x + a.x) * scale; acc.y = (acc.y + a.y) * scale;
        acc.z = (acc.z + a.z) * scale; acc.w = (acc.w + a.w) * scale;
    }
    *(float4*)(out + (long)d * HID_ + lane * 4) = acc;
}

// ---------------- final: softmax((pf + hp[seg]) @ W + b) ----------------
__global__ __launch_bounds__(256) void final_kernel(const float* __restrict__ PF,
                                                    const float* __restrict__ HP,
                                                    const int* __restrict__ seg,
                                                    const float* __restrict__ W,
                                                    const float* __restrict__ bias,
                                                    float* __restrict__ out) {
    __shared__ float Ws[HID_ * NC_];
    __shared__ float bs[NC_];
    for (int i = threadIdx.x; i < HID_ * NC_; i += 256) Ws[i] = W[i];
    if (threadIdx.x < NC_) bs[threadIdx.x] = bias[threadIdx.x];
    __syncthreads();
    int wid = threadIdx.x >> 5, lane = threadIdx.x & 31;
    long row = (long)blockIdx.x * 8 + wid;
    int sg = seg[row];
    float4 p4 = *(const float4*)(PF + row * HID_ + lane * 4);
    float4 h4 = *(const float4*)(HP + (long)sg * HID_ + lane * 4);
    float h[4] = {p4.x + h4.x, p4.y + h4.y, p4.z + h4.z, p4.w + h4.w};
    float l[NC_];
#pragma unroll
    for (int c = 0; c < NC_; c++) {
        l[c] = h[0] * Ws[(lane * 4 + 0) * NC_ + c] + h[1] * Ws[(lane * 4 + 1) * NC_ + c] +
               h[2] * Ws[(lane * 4 + 2) * NC_ + c] + h[3] * Ws[(lane * 4 + 3) * NC_ + c];
    }
#pragma unroll
    for (int o = 16; o >= 1; o >>= 1) {
#pragma unroll
        for (int c = 0; c < NC_; c++) l[c] += __shfl_xor_sync(0xffffffffu, l[c], o);
    }
    float mx = -1e30f;
#pragma unroll
    for (int c = 0; c < NC_; c++) {
        l[c] += bs[c];
        mx = fmaxf(mx, l[c]);
    }
    float sum = 0.f;
#pragma unroll
    for (int c = 0; c < NC_; c++) {
        l[c] = __expf(l[c] - mx);
        sum += l[c];
    }
    float inv = 1.0f / sum;
    if (lane < NC_) {
        float v = 0.f;
#pragma unroll
        for (int c = 0; c < NC_; c++)
            if (lane == c) v = l[c];
        out[row * NC_ + lane] = v * inv;
    }
}

// ---------------- host orchestration ----------------
static void run_bn(const float* X, float* Y, const float* g, const float* b,
                   float* stats, long M, int lrelu) {
    zerof_kernel<<<1, 256>>>(stats, 256);
    int nb = (M >= 100000) ? 1024 : 16;
    bnstats_kernel<<<nb, 256>>>(X, (int)M, stats);
    bnprep_kernel<<<1, 128>>>(stats, g, b, 1.0f / (float)M);
    long total = M * 32;
    bnapply_kernel<<<(int)((total + 255) / 256), 256>>>(X, Y, stats, M, lrelu);
}

extern "C" void kernel_launch(void* const* d_in, const int* in_sizes, int n_in,
                              void* d_out, int out_size) {
    const float* x      = (const float*)d_in[0];
    const int*   seg    = (const int*)d_in[1];
    const int*   a_src  = (const int*)d_in[2];
    const int*   a_dst  = (const int*)d_in[3];
    const float* a_w    = (const float*)d_in[4];
    const int*   m_src  = (const int*)d_in[5];
    const int*   m_dst  = (const int*)d_in[6];
    const float* pre_W  = (const float*)d_in[7];
    const float* pre_b  = (const float*)d_in[8];
    const float* bn0_g  = (const float*)d_in[9];
    const float* bn0_b  = (const float*)d_in[10];
    const float* sf_W   = (const float*)d_in[11];
    const float* sf_b   = (const float*)d_in[12];
    const float* sf_g   = (const float*)d_in[13];
    const float* sf_beta= (const float*)d_in[14];
    const float* pf_Wv  = (const float*)d_in[15];
    const float* pf_bv  = (const float*)d_in[16];
    const float* pf_Wq  = (const float*)d_in[17];
    const float* pf_bq  = (const float*)d_in[18];
    const float* pf_g   = (const float*)d_in[19];
    const float* pf_beta= (const float*)d_in[20];
    const float* out_W  = (const float*)d_in[21];
    const float* out_b  = (const float*)d_in[22];
    float* out = (float*)d_out;

    float *p_x0, *p_t0, *p_pf, *p_Q, *p_V, *p_hp, *p_h, *p_xs, *p_cA, *p_cB, *p_aW, *p_stats, *p_biasQV;
    __half *p_Qh, *p_Vh;
    int *p_hist, *p_aux, *p_peOff, *p_peCur, *p_peDst, *p_aOff, *p_aCur, *p_aSrc;
    int *p_pOff, *p_pCur, *p_pSort;
    unsigned char* p_img;
    cudaGetSymbolAddress((void**)&p_x0, g_x0);
    cudaGetSymbolAddress((void**)&p_t0, g_t0);
    cudaGetSymbolAddress((void**)&p_pf, g_pf);
    cudaGetSymbolAddress((void**)&p_Q,  g_Q);
    cudaGetSymbolAddress((void**)&p_V,  g_V);
    cudaGetSymbolAddress((void**)&p_Qh, g_Qh);
    cudaGetSymbolAddress((void**)&p_Vh, g_Vh);
    cudaGetSymbolAddress((void**)&p_hp, g_hp);
    cudaGetSymbolAddress((void**)&p_h,  g_h);
    cudaGetSymbolAddress((void**)&p_xs, g_xs);
    cudaGetSymbolAddress((void**)&p_cA, g_cA);
    cudaGetSymbolAddress((void**)&p_cB, g_cB);
    cudaGetSymbolAddress((void**)&p_aW, g_aW);
    cudaGetSymbolAddress((void**)&p_stats, g_stats);
    cudaGetSymbolAddress((void**)&p_hist, g_hist);
    cudaGetSymbolAddress((void**)&p_aux, g_aux);
    cudaGetSymbolAddress((void**)&p_peOff, g_peOff);
    cudaGetSymbolAddress((void**)&p_peCur, g_peCur);
    cudaGetSymbolAddress((void**)&p_peDst, g_peDst);
    cudaGetSymbolAddress((void**)&p_aOff, g_aOff);
    cudaGetSymbolAddress((void**)&p_aCur, g_aCur);
    cudaGetSymbolAddress((void**)&p_aSrc, g_aSrc);
    cudaGetSymbolAddress((void**)&p_pOff, g_pOff);
    cudaGetSymbolAddress((void**)&p_pCur, g_pCur);
    cudaGetSymbolAddress((void**)&p_pSort, g_pSort);
    cudaGetSymbolAddress((void**)&p_img, g_Bimg);
    cudaGetSymbolAddress((void**)&p_biasQV, g_biasQV);

    cudaFuncSetAttribute(gemm_mma_kernel, cudaFuncAttributeMaxDynamicSharedMemorySize, SM_GEMM);

    __nv_bfloat16* img_pre = (__nv_bfloat16*)p_img;                  // Kp=256, Nc=128
    __nv_bfloat16* img_qv0 = (__nv_bfloat16*)(p_img + 131072);       // Kp=128, Nc=256
    __nv_bfloat16* img_qv1 = (__nv_bfloat16*)(p_img + 262144);
    __nv_bfloat16* img_sf  = (__nv_bfloat16*)(p_img + 393216);       // Kp=128, Nc=128

    // ---- launches 1-3: prep images needed by the pre-GEMM ----
    prep_w_kernel<<<32, 256>>>(pre_W, C_, 256, img_pre);
    prep_qv_kernel<<<32, 256>>>(pf_Wq, pf_Wv, pf_bq, pf_bv, img_qv0, p_biasQV);
    prep_qv_kernel<<<32, 256>>>(pf_Wq + (size_t)2 * HID_ * 64, pf_Wv + (size_t)2 * HID_ * 64,
                                pf_bq + HID_, pf_bv + HID_, img_qv1, p_biasQV + 256);

    // ---- launch 4 (ncu capture slot): the pre GEMM ----
    gemm_mma_kernel<<<dim3(N_ / 128, 1), 256, SM_GEMM>>>(x, C_, 256, img_pre, 128,
                                                         pre_b, p_t0, (float*)0);

    // ---- remaining preps + BN(x0) ----
    for (int l = 0; l < 5; l++)
        prep_w_kernel<<<16, 256>>>(sf_W + (size_t)l * HID_ * HID_, HID_, 128,
                                   img_sf + (size_t)l * 32768);
    run_bn(p_t0, p_x0, bn0_g, bn0_b, p_stats, N_, 0);

    // ---- sort pixel-graph edges by src -> CSR ----
    zero_kernel<<<N_ / 256, 256>>>(p_hist, N_);
    hist_kernel<<<EM_ / 256, 256>>>(m_src, EM_, p_hist);
    scan_block_kernel<<<N_ / 1024, 1024>>>(p_hist, N_, p_peOff, p_aux);
    scan_aux_kernel<<<1, 1024>>>(p_aux, N_ / 1024);
    scan_add_kernel<<<N_ / 256, 256>>>(p_peOff, N_, p_aux, p_peCur, EM_);
    scatter_edge_kernel<<<EM_ / 256, 256>>>(m_src, m_dst, EM_, p_peCur, p_peDst);

    // ---- sort superpixel-graph edges by dst -> CSR ----
    zero_kernel<<<S_ / 256, 256>>>(p_hist, S_);
    hist_kernel<<<EA_ / 256, 256>>>(a_dst, EA_, p_hist);
    scan_block_kernel<<<S_ / 1024, 1024>>>(p_hist, S_, p_aOff, p_aux);
    scan_aux_kernel<<<1, 1024>>>(p_aux, S_ / 1024);
    scan_add_kernel<<<S_ / 256, 256>>>(p_aOff, S_, p_aux, p_aCur, EA_);
    scatter_aedge_kernel<<<EA_ / 256, 256>>>(a_dst, a_src, a_w, EA_, p_aCur, p_aSrc, p_aW);

    // ---- sort pixels by seg -> CSR ----
    zero_kernel<<<S_ / 256, 256>>>(p_hist, S_);
    hist_kernel<<<N_ / 256, 256>>>(seg, N_, p_hist);
    scan_block_kernel<<<S_ / 1024, 1024>>>(p_hist, S_, p_pOff, p_aux);
    scan_aux_kernel<<<1, 1024>>>(p_aux, S_ / 1024);
    scan_add_kernel<<<S_ / 256, 256>>>(p_pOff, S_, p_aux, p_pCur, N_);
    scatter_pix_kernel<<<N_ / 256, 256>>>(seg, N_, p_pCur, p_pSort);

    // ---- PF branch: 2 attention layers on pixel graph ----
    const float* pfin = p_x0;
    for (int l = 0; l < 2; l++) {
        gemm_mma_kernel<<<dim3(N_ / 128, 2), 256, SM_GEMM>>>(pfin, HID_, 128,
                                                             (l == 0) ? img_qv0 : img_qv1, 256,
                                                             p_biasQV + l * 256, p_Q, p_V);
        ln_kernel<<<N_ / 8, 256>>>(p_Q, p_Qh);
        convh_kernel<<<(int)(((long)N_ * 32 + 255) / 256), 256>>>(p_V, p_Vh, (long)N_ * 32);
        attn_kernel<<<N_ / 8, 256>>>(p_Qh, p_Vh, p_peOff, p_peDst, p_t0);
        run_bn(p_t0, p_pf, pf_g + l * HID_, pf_beta + l * HID_, p_stats, N_, 1);
        pfin = p_pf;
    }

    // ---- Hyperpixel branch: pool + 5 SF layers ----
    pool_kernel<<<S_ / 8, 256>>>(p_x0, p_pOff, p_pSort, p_hp);
    const float inv2g = 1.0f / 2.9f;
    for (int l = 0; l < 5; l++) {
        gemm_mma_kernel<<<dim3(S_ / 128, 1), 256, SM_GEMM>>>(p_hp, HID_, 128,
                                                             img_sf + (size_t)l * 32768, 128,
                                                             sf_b + l * HID_, p_h, (float*)0);
        prop_kernel<<<S_ / 8, 256>>>(p_h, p_aOff, p_aSrc, p_aW, (const float*)0, 1.0f, p_xs);
        const float* cur = p_hp;
        float* nxt = p_cA;
        for (int it = 0; it < 5; it++) {
            prop_kernel<<<S_ / 8, 256>>>(cur, p_aOff, p_aSrc, p_aW, p_xs, inv2g, nxt);
            cur = nxt;
            nxt = (cur == p_cA) ? p_cB : p_cA;
        }
        run_bn(cur, p_hp, sf_g + l * HID_, sf_beta + l * HID_, p_stats, S_, 1);
    }

    // ---- final fused output ----
    final_kernel<<<N_ / 8, 256>>>(p_pf, p_hp, seg, out_W, out_b, out);
}

// round 16
// speedup vs baseline: 1.3426x; 1.0107x over previous
#include <cuda_runtime.h>
#include <cuda_bf16.h>
#include <cuda_fp16.h>
#include <cstdint>
#include <cstddef>
#include <math.h>

#define N_  262144
#define C_  200
#define HID_ 128
#define S_  4096
#define EA_ 65536
#define EM_ 2097152
#define NC_ 16

// ---------------- device scratch ----------------
__device__ float g_x0[(size_t)N_ * HID_];
__device__ float g_t0[(size_t)N_ * HID_];
__device__ float g_pf[(size_t)N_ * HID_];
__device__ float g_Q [(size_t)N_ * HID_];
__device__ __align__(16) __half g_Qh[(size_t)N_ * HID_];
__device__ __align__(16) __half g_Vh[(size_t)N_ * HID_];

__device__ float g_hp[S_ * HID_];
__device__ float g_h [S_ * HID_];
__device__ float g_xs[S_ * HID_];
__device__ float g_cA[S_ * HID_];
__device__ float g_cB[S_ * HID_];

__device__ int   g_hist[N_];
__device__ int   g_aux[1024];
__device__ int   g_peOff[N_ + 1];
__device__ int   g_peCur[N_];
__device__ int   g_peDst[EM_];
__device__ int   g_aOff[S_ + 1];
__device__ int   g_aCur[S_];
__device__ int   g_aSrc[EA_];
__device__ float g_aW [EA_];
__device__ int   g_pOff[S_ + 1];
__device__ int   g_pCur[S_];
__device__ int   g_pSort[N_];
__device__ float g_stats[256];

__device__ __align__(256) unsigned char g_Bimg[720896];
__device__ float g_biasQV[512];

// ---------------- split helpers ----------------
__device__ __forceinline__ void split4(float4 v, uint32_t& h01, uint32_t& h23,
                                       uint32_t& l01, uint32_t& l23) {
    __nv_bfloat16 h0 = __float2bfloat16(v.x), h1 = __float2bfloat16(v.y);
    __nv_bfloat16 h2 = __float2bfloat16(v.z), h3 = __float2bfloat16(v.w);
    __nv_bfloat16 l0 = __float2bfloat16(v.x - __bfloat162float(h0));
    __nv_bfloat16 l1 = __float2bfloat16(v.y - __bfloat162float(h1));
    __nv_bfloat16 l2 = __float2bfloat16(v.z - __bfloat162float(h2));
    __nv_bfloat16 l3 = __float2bfloat16(v.w - __bfloat162float(h3));
    h01 = ((uint32_t)__bfloat16_as_ushort(h1) << 16) | (uint32_t)__bfloat16_as_ushort(h0);
    h23 = ((uint32_t)__bfloat16_as_ushort(h3) << 16) | (uint32_t)__bfloat16_as_ushort(h2);
    l01 = ((uint32_t)__bfloat16_as_ushort(l1) << 16) | (uint32_t)__bfloat16_as_ushort(l0);
    l23 = ((uint32_t)__bfloat16_as_ushort(l3) << 16) | (uint32_t)__bfloat16_as_ushort(l2);
}

__device__ __forceinline__ void mma16816(float* c, const uint32_t* a, const uint32_t* b) {
    asm volatile(
        "mma.sync.aligned.m16n8k16.row.col.f32.bf16.bf16.f32 "
        "{%0,%1,%2,%3}, {%4,%5,%6,%7}, {%8,%9}, {%0,%1,%2,%3};"
        : "+f"(c[0]), "+f"(c[1]), "+f"(c[2]), "+f"(c[3])
        : "r"(a[0]), "r"(a[1]), "r"(a[2]), "r"(a[3]), "r"(b[0]), "r"(b[1]));
}

// ---------------- prep kernels ----------------
__global__ void prep_w_kernel(const float* __restrict__ W, int Kreal, int Kp,
                              __nv_bfloat16* __restrict__ img) {
    int idx = blockIdx.x * 256 + threadIdx.x;
    int kq = Kp >> 2;
    if (idx >= 128 * kq) return;
    int n = idx / kq;
    int k = (idx - n * kq) * 4;
    float4 v;
    v.x = (k + 0 < Kreal) ? W[(k + 0) * 128 + n] : 0.f;
    v.y = (k + 1 < Kreal) ? W[(k + 1) * 128 + n] : 0.f;
    v.z = (k + 2 < Kreal) ? W[(k + 2) * 128 + n] : 0.f;
    v.w = (k + 3 < Kreal) ? W[(k + 3) * 128 + n] : 0.f;
    uint32_t h01, h23, l01, l23;
    split4(v, h01, h23, l01, l23);
    *(uint2*)(img + (size_t)n * Kp + k)                    = make_uint2(h01, h23);
    *(uint2*)(img + (size_t)128 * Kp + (size_t)n * Kp + k) = make_uint2(l01, l23);
}

__global__ void prep_qv_kernel(const float* __restrict__ Wq, const float* __restrict__ Wv,
                               const float* __restrict__ bq, const float* __restrict__ bv,
                               __nv_bfloat16* __restrict__ img, float* __restrict__ biasOut) {
    int idx = blockIdx.x * 256 + threadIdx.x;
    if (idx >= 256 * 32) return;
    int n = idx >> 5;
    int k = (idx & 31) * 4;
    const float* W = (n < 128) ? Wq : Wv;
    int nn = (n < 128) ? n : n - 128;
    int h = nn >> 6, col = nn & 63;
    float4 v;
    v.x = W[((h * 128) + k + 0) * 64 + col];
    v.y = W[((h * 128) + k + 1) * 64 + col];
    v.z = W[((h * 128) + k + 2) * 64 + col];
    v.w = W[((h * 128) + k + 3) * 64 + col];
    uint32_t h01, h23, l01, l23;
    split4(v, h01, h23, l01, l23);
    *(uint2*)(img + (size_t)n * 128 + k)                     = make_uint2(h01, h23);
    *(uint2*)(img + (size_t)256 * 128 + (size_t)n * 128 + k) = make_uint2(l01, l23);
    if ((idx & 31) == 0) biasOut[n] = (n < 128) ? bq[h * 64 + col] : bv[h * 64 + col];
}

// ---------------- warp-MMA GEMM, double-buffered pipeline ----------------
// nh==0 writes float to outA; nh==1 writes __half to outBh. (resubmit: R12 artifact, infra failed twice)
#define LDA 72
#define STAGE_B (4 * 128 * LDA * 2)
#define SM_GEMM (2 * STAGE_B + 512)
__global__ __launch_bounds__(256) void gemm_mma_kernel(
    const float* __restrict__ A, int Kreal, int Kp,
    const __nv_bfloat16* __restrict__ Bimg, int Nc,
    const float* __restrict__ bias,
    float* __restrict__ outA, __half* __restrict__ outBh) {
    extern __shared__ char smem[];
    float* bsm = (float*)(smem + 2 * STAGE_B);
    int tid = threadIdx.x;
    int lane = tid & 31, wid = tid >> 5;
    int wm = wid & 3, wn = wid >> 2;
    long rowBase = (long)blockIdx.x * 128;
    int nh = blockIdx.y;
    const __nv_bfloat16* BsrcH = Bimg + (size_t)(nh * 128) * Kp;
    const __nv_bfloat16* BsrcL = Bimg + (size_t)Nc * Kp + (size_t)(nh * 128) * Kp;
    if (tid < 128) bsm[tid] = bias[nh * 128 + tid];

    int nch = Kp >> 6;
    int aRow = tid >> 4;
    int aCol0 = (tid & 15) * 4;

    float acc[2][8][4];
#pragma unroll
    for (int t = 0; t < 2; t++)
#pragma unroll
        for (int j = 0; j < 8; j++)
#pragma unroll
            for (int q = 0; q < 4; q++) acc[t][j][q] = 0.f;

    float4 aPre[8];
#pragma unroll
    for (int i = 0; i < 8; i++) {
        int row = aRow + i * 16;
        int k = aCol0;
        float4 v = make_float4(0.f, 0.f, 0.f, 0.f);
        if (k < Kreal) {
            const float* ap = A + (rowBase + row) * (long)Kreal + k;
            if (k + 3 < Kreal) v = *(const float4*)ap;
            else {
                v.x = ap[0];
                if (k + 1 < Kreal) v.y = ap[1];
                if (k + 2 < Kreal) v.z = ap[2];
            }
        }
        aPre[i] = v;
    }
    {
        char* st = smem;
        __nv_bfloat16* Bh = (__nv_bfloat16*)(st + 2 * 128 * LDA * 2);
        __nv_bfloat16* Bl = Bh + 128 * LDA;
#pragma unroll
        for (int i = 0; i < 8; i++) {
            int flat = tid + i * 256;
            int plane = flat >> 10;
            int r = (flat >> 3) & 127;
            int q = flat & 7;
            const __nv_bfloat16* src = (plane ? BsrcL : BsrcH) + (size_t)r * Kp + q * 8;
            __nv_bfloat16* dst = (plane ? Bl : Bh) + r * LDA + q * 8;
            uint32_t da = (uint32_t)__cvta_generic_to_shared(dst);
            asm volatile("cp.async.ca.shared.global [%0], [%1], 16;" :: "r"(da), "l"(src));
        }
        asm volatile("cp.async.commit_group;" ::: "memory");
    }

    for (int ch = 0; ch < nch; ch++) {
        int cur = ch & 1;
        char* st = smem + cur * STAGE_B;
        __nv_bfloat16* Ah = (__nv_bfloat16*)st;
        __nv_bfloat16* Al = Ah + 128 * LDA;
        __nv_bfloat16* Bh = Al + 128 * LDA;
        __nv_bfloat16* Bl = Bh + 128 * LDA;

#pragma unroll
        for (int i = 0; i < 8; i++) {
            int row = aRow + i * 16;
            uint32_t h01, h23, l01, l23;
            split4(aPre[i], h01, h23, l01, l23);
            *(uint2*)(Ah + row * LDA + aCol0) = make_uint2(h01, h23);
            *(uint2*)(Al + row * LDA + aCol0) = make_uint2(l01, l23);
        }
        if (ch + 1 < nch) {
#pragma unroll
            for (int i = 0; i < 8; i++) {
                int row = aRow + i * 16;
                int k = (ch + 1) * 64 + aCol0;
                float4 v = make_float4(0.f, 0.f, 0.f, 0.f);
                if (k < Kreal) {
                    const float* ap = A + (rowBase + row) * (long)Kreal + k;
                    if (k + 3 < Kreal) v = *(const float4*)ap;
                    else {
                        v.x = ap[0];
                        if (k + 1 < Kreal) v.y = ap[1];
                        if (k + 2 < Kreal) v.z = ap[2];
                    }
                }
                aPre[i] = v;
            }
        }
        asm volatile("cp.async.wait_group 0;" ::: "memory");
        __syncthreads();
        if (ch + 1 < nch) {
            char* st2 = smem + (1 - cur) * STAGE_B;
            __nv_bfloat16* Bh2 = (__nv_bfloat16*)(st2 + 2 * 128 * LDA * 2);
            __nv_bfloat16* Bl2 = Bh2 + 128 * LDA;
#pragma unroll
            for (int i = 0; i < 8; i++) {
                int flat = tid + i * 256;
                int plane = flat >> 10;
                int r = (flat >> 3) & 127;
                int q = flat & 7;
                const __nv_bfloat16* src = (plane ? BsrcL : BsrcH) + (size_t)r * Kp +
                                           (ch + 1) * 64 + q * 8;
                __nv_bfloat16* dst = (plane ? Bl2 : Bh2) + r * LDA + q * 8;
                uint32_t da = (uint32_t)__cvta_generic_to_shared(dst);
                asm volatile("cp.async.ca.shared.global [%0], [%1], 16;" :: "r"(da), "l"(src));
            }
            asm volatile("cp.async.commit_group;" ::: "memory");
        }

#pragma unroll
        for (int ks = 0; ks < 4; ks++) {
            int kk = ks * 16;
            uint32_t ah[2][4], al[2][4];
#pragma unroll
            for (int t = 0; t < 2; t++) {
                int r0 = wm * 32 + t * 16 + (lane >> 2);
                int cA = kk + (lane & 3) * 2;
                ah[t][0] = *(const uint32_t*)(Ah + r0 * LDA + cA);
                ah[t][1] = *(const uint32_t*)(Ah + (r0 + 8) * LDA + cA);
                ah[t][2] = *(const uint32_t*)(Ah + r0 * LDA + cA + 8);
                ah[t][3] = *(const uint32_t*)(Ah + (r0 + 8) * LDA + cA + 8);
                al[t][0] = *(const uint32_t*)(Al + r0 * LDA + cA);
                al[t][1] = *(const uint32_t*)(Al + (r0 + 8) * LDA + cA);
                al[t][2] = *(const uint32_t*)(Al + r0 * LDA + cA + 8);
                al[t][3] = *(const uint32_t*)(Al + (r0 + 8) * LDA + cA + 8);
            }
            uint32_t bh[8][2], bl[8][2];
#pragma unroll
            for (int j = 0; j < 8; j++) {
                int cn = wn * 64 + j * 8 + (lane >> 2);
                int cB = kk + (lane & 3) * 2;
                bh[j][0] = *(const uint32_t*)(Bh + cn * LDA + cB);
                bh[j][1] = *(const uint32_t*)(Bh + cn * LDA + cB + 8);
                bl[j][0] = *(const uint32_t*)(Bl + cn * LDA + cB);
                bl[j][1] = *(const uint32_t*)(Bl + cn * LDA + cB + 8);
            }
#pragma unroll
            for (int t = 0; t < 2; t++)
#pragma unroll
                for (int j = 0; j < 8; j++) {
                    mma16816(acc[t][j], ah[t], bh[j]);
                    mma16816(acc[t][j], al[t], bh[j]);
                    mma16816(acc[t][j], ah[t], bl[j]);
                }
        }
        __syncthreads();
    }

#pragma unroll
    for (int t = 0; t < 2; t++) {
        long r0 = rowBase + wm * 32 + t * 16 + (lane >> 2);
#pragma unroll
        for (int j = 0; j < 8; j++) {
            int cloc = wn * 64 + j * 8 + (lane & 3) * 2;
            float2 v0 = make_float2(acc[t][j][0] + bsm[cloc], acc[t][j][1] + bsm[cloc + 1]);
            float2 v1 = make_float2(acc[t][j][2] + bsm[cloc], acc[t][j][3] + bsm[cloc + 1]);
            if (nh == 0) {
                *(float2*)(outA + r0 * 128 + cloc)       = v0;
                *(float2*)(outA + (r0 + 8) * 128 + cloc) = v1;
            } else {
                *(__half2*)(outBh + r0 * 128 + cloc)       = __floats2half2_rn(v0.x, v0.y);
                *(__half2*)(outBh + (r0 + 8) * 128 + cloc) = __floats2half2_rn(v1.x, v1.y);
            }
        }
    }
}

// ---------------- utilities ----------------
__global__ void zero_kernel(int* p, int n) {
    int i = blockIdx.x * blockDim.x + threadIdx.x;
    if (i < n) p[i] = 0;
}
__global__ void zerof_kernel(float* p, int n) {
    int i = blockIdx.x * blockDim.x + threadIdx.x;
    if (i < n) p[i] = 0.f;
}

__global__ void hist_kernel(const int* __restrict__ keys, int n, int* __restrict__ hist) {
    int i = blockIdx.x * blockDim.x + threadIdx.x;
    if (i < n) atomicAdd(&hist[keys[i]], 1);
}

__global__ void scan_block_kernel(const int* __restrict__ in, int n,
                                  int* __restrict__ excl_out, int* __restrict__ bsum) {
    __shared__ int sh[1024];
    int tid = threadIdx.x;
    int idx = blockIdx.x * 1024 + tid;
    int v = (idx < n) ? in[idx] : 0;
    sh[tid] = v;
    __syncthreads();
    for (int off = 1; off < 1024; off <<= 1) {
        int t = (tid >= off) ? sh[tid - off] : 0;
        __syncthreads();
        sh[tid] += t;
        __syncthreads();
    }
    if (idx < n) excl_out[idx] = sh[tid] - v;
    if (tid == 1023) bsum[blockIdx.x] = sh[tid];
}

__global__ void scan_aux_kernel(int* aux, int nb) {
    __shared__ int sh[1024];
    int tid = threadIdx.x;
    int v = (tid < nb) ? aux[tid] : 0;
    sh[tid] = v;
    __syncthreads();
    for (int off = 1; off < 1024; off <<= 1) {
        int t = (tid >= off) ? sh[tid - off] : 0;
        __syncthreads();
        sh[tid] += t;
        __syncthreads();
    }
    if (tid < nb) aux[tid] = sh[tid] - v;
}

__global__ void scan_add_kernel(int* off, int n, const int* __restrict__ aux,
                                int* __restrict__ cursor, int total) {
    int idx = blockIdx.x * blockDim.x + threadIdx.x;
    if (idx < n) {
        int v = off[idx] + aux[idx >> 10];
        off[idx] = v;
        cursor[idx] = v;
    }
    if (idx == 0) off[n] = total;
}

__global__ void scatter_edge_kernel(const int* __restrict__ src, const int* __restrict__ dst,
                                    int n, int* __restrict__ cur, int* __restrict__ outDst) {
    int i = blockIdx.x * blockDim.x + threadIdx.x;
    if (i < n) {
        int p = atomicAdd(&cur[src[i]], 1);
        outDst[p] = dst[i];
    }
}

__global__ void scatter_aedge_kernel(const int* __restrict__ dstKey, const int* __restrict__ srcVal,
                                     const float* __restrict__ wVal, int n,
                                     int* __restrict__ cur, int* __restrict__ outSrc,
                                     float* __restrict__ outW) {
    int i = blockIdx.x * blockDim.x + threadIdx.x;
    if (i < n) {
        int p = atomicAdd(&cur[dstKey[i]], 1);
        outSrc[p] = srcVal[i];
        outW[p]   = wVal[i];
    }
}

__global__ void scatter_pix_kernel(const int* __restrict__ seg, int n,
                                   int* __restrict__ cur, int* __restrict__ outPix) {
    int i = blockIdx.x * blockDim.x + threadIdx.x;
    if (i < n) {
        int p = atomicAdd(&cur[seg[i]], 1);
        outPix[p] = i;
    }
}

// ---------------- BatchNorm ----------------
__global__ __launch_bounds__(256) void bnstats_kernel(const float* __restrict__ X, int M,
                                                      float* __restrict__ stats) {
    int lane = threadIdx.x & 31;
    int rs = threadIdx.x >> 5;
    float4 s = make_float4(0.f, 0.f, 0.f, 0.f);
    float4 q = make_float4(0.f, 0.f, 0.f, 0.f);
    for (long r = blockIdx.x * 8 + rs; r < M; r += (long)gridDim.x * 8) {
        float4 v = *(const float4*)(X + r * HID_ + lane * 4);
        s.x += v.x; s.y += v.y; s.z += v.z; s.w += v.w;
        q.x += v.x * v.x; q.y += v.y * v.y; q.z += v.z * v.z; q.w += v.w * v.w;
    }
    __shared__ float shs[8][HID_];
    __shared__ float shq[8][HID_];
    shs[rs][lane * 4 + 0] = s.x; shs[rs][lane * 4 + 1] = s.y;
    shs[rs][lane * 4 + 2] = s.z; shs[rs][lane * 4 + 3] = s.w;
    shq[rs][lane * 4 + 0] = q.x; shq[rs][lane * 4 + 1] = q.y;
    shq[rs][lane * 4 + 2] = q.z; shq[rs][lane * 4 + 3] = q.w;
    __syncthreads();
    if (threadIdx.x < HID_) {
        int c = threadIdx.x;
        float ss = 0.f, qq = 0.f;
#pragma unroll
        for (int r = 0; r < 8; r++) { ss += shs[r][c]; qq += shq[r][c]; }
        atomicAdd(&stats[c], ss);
        atomicAdd(&stats[HID_ + c], qq);
    }
}

__global__ void bnprep_kernel(float* stats, const float* __restrict__ g,
                              const float* __restrict__ b, float invM) {
    int c = threadIdx.x;
    float m = stats[c] * invM;
    float var = stats[HID_ + c] * invM - m * m;
    float w = rsqrtf(var + 1e-5f);
    float sc = w * g[c];
    stats[HID_ + c] = sc;
    stats[c] = b[c] - m * sc;
}

__global__ void bnapply_kernel(const float* __restrict__ X, float* __restrict__ Y,
                               const float* __restrict__ stats, long M, int lrelu) {
    long idx = (long)blockIdx.x * blockDim.x + threadIdx.x;
    long total = M * 32;
    if (idx >= total) return;
    int c4 = (int)(idx & 31);
    float4 v = *(const float4*)(X + idx * 4);
    float in[4] = {v.x, v.y, v.z, v.w};
    float o[4];
#pragma unroll
    for (int j = 0; j < 4; j++) {
        int c = c4 * 4 + j;
        float y = in[j] * stats[HID_ + c] + stats[c];
        if (lrelu) y = (y >= 0.f) ? y : 0.01f * y;
        o[j] = y;
    }
    *(float4*)(Y + idx * 4) = make_float4(o[0], o[1], o[2], o[3]);
}

// ---------------- LayerNorm per 64-wide head; outputs half ----------------
__global__ __launch_bounds__(256) void ln_kernel(const float* __restrict__ Q,
                                                 __half* __restrict__ Qh) {
    int wid = threadIdx.x >> 5, lane = threadIdx.x & 31;
    long row = (long)blockIdx.x * 8 + wid;
    float4 v = *(const float4*)(Q + row * HID_ + lane * 4);
    float s = v.x + v.y + v.z + v.w;
    float q = v.x * v.x + v.y * v.y + v.z * v.z + v.w * v.w;
#pragma unroll
    for (int o = 8; o >= 1; o >>= 1) {
        s += __shfl_xor_sync(0xffffffffu, s, o);
        q += __shfl_xor_sync(0xffffffffu, q, o);
    }
    float m = s * (1.0f / 64.0f);
    float var = q * (1.0f / 64.0f) - m * m;
    float w = rsqrtf(var + 1e-5f);
    __half2 a = __floats2half2_rn((v.x - m) * w, (v.y - m) * w);
    __half2 b = __floats2half2_rn((v.z - m) * w, (v.w - m) * w);
    uint2 o2;
    o2.x = *(uint32_t*)&a;
    o2.y = *(uint32_t*)&b;
    *(uint2*)(Qh + row * HID_ + lane * 4) = o2;
}

// ---------------- fused attention: half-warp per edge, 2 edges/warp-iter ----------------
#define MAXE 64
__global__ __launch_bounds__(256) void attn_kernel(
    const __half* __restrict__ Q, const __half* __restrict__ V,
    const int* __restrict__ off, const int* __restrict__ dsts,
    float* __restrict__ out) {
    __shared__ float she[8][MAXE][2];
    int tid = threadIdx.x;
    int wid = tid >> 5, lane = tid & 31;
    int hw = lane >> 4;          // half-warp id
    int hl = lane & 15;          // lane within half-warp
    int hgrp = hl >> 3;          // head index (dims 0-63 vs 64-127)
    unsigned hmask = hw ? 0xffff0000u : 0x0000ffffu;
    int src = blockIdx.x * 8 + wid;
    int o0 = off[src], o1 = off[src + 1];
    int deg = o1 - o0;

    uint4 qr = *(const uint4*)(Q + (long)src * HID_ + hl * 8);
    float qv[8];
    {
        __half2* qh = (__half2*)&qr;
#pragma unroll
        for (int k = 0; k < 4; k++) {
            float2 f = __half22float2(qh[k]);
            qv[2 * k] = f.x; qv[2 * k + 1] = f.y;
        }
    }

    float z = 0.f;
    int nIter = (deg + 1) >> 1;
    for (int it = 0; it < nIter; it++) {
        int i = it * 2 + hw;
        bool valid = (i < deg);
        int d = dsts[o0 + (valid ? i : 0)];
        uint4 dr = *(const uint4*)(Q + (long)d * HID_ + hl * 8);
        __half2* dh = (__half2*)&dr;
        float p = 0.f;
#pragma unroll
        for (int k = 0; k < 4; k++) {
            float2 f = __half22float2(dh[k]);
            p += qv[2 * k] * f.x + qv[2 * k + 1] * f.y;
        }
        p += __shfl_xor_sync(hmask, p, 4);
        p += __shfl_xor_sync(hmask, p, 2);
        p += __shfl_xor_sync(hmask, p, 1);
        float e = valid ? __expf(p * (1.0f / HID_)) : 0.f;
        z += e;
        if (valid && i < MAXE && (hl & 7) == 0) she[wid][i][hgrp] = e;
    }
    z += __shfl_xor_sync(0xffffffffu, z, 16);
    float invz = (deg > 0) ? 1.0f / z : 0.f;
    __syncwarp();

    float acc[8];
#pragma unroll
    for (int k = 0; k < 8; k++) acc[k] = 0.f;
    for (int it = 0; it < nIter; it++) {
        int i = it * 2 + hw;
        bool valid = (i < deg);
        int d = dsts[o0 + (valid ? i : 0)];
        float e;
        if (i < MAXE) {
            e = valid ? she[wid][i][hgrp] : 0.f;
        } else {
            uint4 dr = *(const uint4*)(Q + (long)d * HID_ + hl * 8);
            __half2* dh = (__half2*)&dr;
            float p = 0.f;
#pragma unroll
            for (int k = 0; k < 4; k++) {
                float2 f = __half22float2(dh[k]);
                p += qv[2 * k] * f.x + qv[2 * k + 1] * f.y;
            }
            p += __shfl_xor_sync(hmask, p, 4);
            p += __shfl_xor_sync(hmask, p, 2);
            p += __shfl_xor_sync(hmask, p, 1);
            e = valid ? __expf(p * (1.0f / HID_)) : 0.f;
        }
        float a = e * invz;
        uint4 vr = *(const uint4*)(V + (long)d * HID_ + hl * 8);
        __half2* vh = (__half2*)&vr;
#pragma unroll
        for (int k = 0; k < 4; k++) {
            float2 f = __half22float2(vh[k]);
            acc[2 * k]     += a * f.x;
            acc[2 * k + 1] += a * f.y;
        }
    }
#pragma unroll
    for (int k = 0; k < 8; k++) acc[k] += __shfl_xor_sync(0xffffffffu, acc[k], 16);
    if (hw == 0) {
        long base = (long)src * HID_ + hl * 8;
        *(float4*)(out + base)     = make_float4(acc[0], acc[1], acc[2], acc[3]);
        *(float4*)(out + base + 4) = make_float4(acc[4], acc[5], acc[6], acc[7]);
    }
}

// ---------------- superpixel mean pooling ----------------
__global__ __launch_bounds__(256) void pool_kernel(const float* __restrict__ X,
                                                   const int* __restrict__ off,
                                                   const int* __restrict__ pix,
                                                   float* __restrict__ hp) {
    int wid = threadIdx.x >> 5, lane = threadIdx.x & 31;
    int s = blockIdx.x * 8 + wid;
    int o0 = off[s], o1 = off[s + 1];
    float4 acc = make_float4(0.f, 0.f, 0.f, 0.f);
    for (int i = o0; i < o1; i++) {
        int p = pix[i];
        float4 v = *(const float4*)(X + (long)p * HID_ + lane * 4);
        acc.x += v.x; acc.y += v.y; acc.z += v.z; acc.w += v.w;
    }
    int deg = o1 - o0;
    float inv = 1.0f / (float)(deg > 0 ? deg : 1);
    acc.x *= inv; acc.y *= inv; acc.z *= inv; acc.w *= inv;
    *(float4*)(hp + (long)s * HID_ + lane * 4) = acc;
}

// ---------------- weighted sparse prop (dst-CSR) ----------------
__global__ __launch_bounds__(256) void prop_kernel(const float* __restrict__ X,
                                                   const int* __restrict__ off,
                                                   const int* __restrict__ srcs,
                                                   const float* __restrict__ w,
                                                   const float* __restrict__ add, float scale,
                                                   float* __restrict__ out) {
    int wid = threadIdx.x >> 5, lane = threadIdx.x & 31;
    int d = blockIdx.x * 8 + wid;
    int o0 = off[d], o1 = off[d + 1];
    float4 acc = make_float4(0.f, 0.f, 0.f, 0.f);
    for (int i = o0; i < o1; i++) {
        int sN = srcs[i];
        float ww = w[i];
        float4 v = *(const float4*)(X + (long)sN * HID_ + lane * 4);
        acc.x += ww * v.x; acc.y += ww * v.y;
        acc.z += ww * v.z; acc.w += ww * v.w;
    }
    if (add) {
        float4 a = *(const float4*)(add + (long)d * HID_ + lane * 4);
        acc.x = (acc.x + a.x) * scale; acc.y = (acc.y + a.y) * scale;
        acc.z = (acc.z + a.z) * scale; acc.w = (acc.w + a.w) * scale;
    }
    *(float4*)(out + (long)d * HID_ + lane * 4) = acc;
}

// ---------------- final: softmax((pf + hp[seg]) @ W + b) ----------------
__global__ __launch_bounds__(256) void final_kernel(const float* __restrict__ PF,
                                                    const float* __restrict__ HP,
                                                    const int* __restrict__ seg,
                                                    const float* __restrict__ W,
                                                    const float* __restrict__ bias,
                                                    float* __restrict__ out) {
    __shared__ float Ws[HID_ * NC_];
    __shared__ float bs[NC_];
    for (int i = threadIdx.x; i < HID_ * NC_; i += 256) Ws[i] = W[i];
    if (threadIdx.x < NC_) bs[threadIdx.x] = bias[threadIdx.x];
    __syncthreads();
    int wid = threadIdx.x >> 5, lane = threadIdx.x & 31;
    long row = (long)blockIdx.x * 8 + wid;
    int sg = seg[row];
    float4 p4 = *(const float4*)(PF + row * HID_ + lane * 4);
    float4 h4 = *(const float4*)(HP + (long)sg * HID_ + lane * 4);
    float h[4] = {p4.x + h4.x, p4.y + h4.y, p4.z + h4.z, p4.w + h4.w};
    float l[NC_];
#pragma unroll
    for (int c = 0; c < NC_; c++) {
        l[c] = h[0] * Ws[(lane * 4 + 0) * NC_ + c] + h[1] * Ws[(lane * 4 + 1) * NC_ + c] +
               h[2] * Ws[(lane * 4 + 2) * NC_ + c] + h[3] * Ws[(lane * 4 + 3) * NC_ + c];
    }
#pragma unroll
    for (int o = 16; o >= 1; o >>= 1) {
#pragma unroll
        for (int c = 0; c < NC_; c++) l[c] += __shfl_xor_sync(0xffffffffu, l[c], o);
    }
    float mx = -1e30f;
#pragma unroll
    for (int c = 0; c < NC_; c++) {
        l[c] += bs[c];
        mx = fmaxf(mx, l[c]);
    }
    float sum = 0.f;
#pragma unroll
    for (int c = 0; c < NC_; c++) {
        l[c] = __expf(l[c] - mx);
        sum += l[c];
    }
    float inv = 1.0f / sum;
    if (lane < NC_) {
        float v = 0.f;
#pragma unroll
        for (int c = 0; c < NC_; c++)
            if (lane == c) v = l[c];
        out[row * NC_ + lane] = v * inv;
    }
}

// ---------------- host orchestration ----------------
static void run_bn(const float* X, float* Y, const float* g, const float* b,
                   float* stats, long M, int lrelu) {
    zerof_kernel<<<1, 256>>>(stats, 256);
    int nb = (M >= 100000) ? 1024 : 16;
    bnstats_kernel<<<nb, 256>>>(X, (int)M, stats);
    bnprep_kernel<<<1, 128>>>(stats, g, b, 1.0f / (float)M);
    long total = M * 32;
    bnapply_kernel<<<(int)((total + 255) / 256), 256>>>(X, Y, stats, M, lrelu);
}

extern "C" void kernel_launch(void* const* d_in, const int* in_sizes, int n_in,
                              void* d_out, int out_size) {
    const float* x      = (const float*)d_in[0];
    const int*   seg    = (const int*)d_in[1];
    const int*   a_src  = (const int*)d_in[2];
    const int*   a_dst  = (const int*)d_in[3];
    const float* a_w    = (const float*)d_in[4];
    const int*   m_src  = (const int*)d_in[5];
    const int*   m_dst  = (const int*)d_in[6];
    const float* pre_W  = (const float*)d_in[7];
    const float* pre_b  = (const float*)d_in[8];
    const float* bn0_g  = (const float*)d_in[9];
    const float* bn0_b  = (const float*)d_in[10];
    const float* sf_W   = (const float*)d_in[11];
    const float* sf_b   = (const float*)d_in[12];
    const float* sf_g   = (const float*)d_in[13];
    const float* sf_beta= (const float*)d_in[14];
    const float* pf_Wv  = (const float*)d_in[15];
    const float* pf_bv  = (const float*)d_in[16];
    const float* pf_Wq  = (const float*)d_in[17];
    const float* pf_bq  = (const float*)d_in[18];
    const float* pf_g   = (const float*)d_in[19];
    const float* pf_beta= (const float*)d_in[20];
    const float* out_W  = (const float*)d_in[21];
    const float* out_b  = (const float*)d_in[22];
    float* out = (float*)d_out;

    float *p_x0, *p_t0, *p_pf, *p_Q, *p_hp, *p_h, *p_xs, *p_cA, *p_cB, *p_aW, *p_stats, *p_biasQV;
    __half *p_Qh, *p_Vh;
    int *p_hist, *p_aux, *p_peOff, *p_peCur, *p_peDst, *p_aOff, *p_aCur, *p_aSrc;
    int *p_pOff, *p_pCur, *p_pSort;
    unsigned char* p_img;
    cudaGetSymbolAddress((void**)&p_x0, g_x0);
    cudaGetSymbolAddress((void**)&p_t0, g_t0);
    cudaGetSymbolAddress((void**)&p_pf, g_pf);
    cudaGetSymbolAddress((void**)&p_Q,  g_Q);
    cudaGetSymbolAddress((void**)&p_Qh, g_Qh);
    cudaGetSymbolAddress((void**)&p_Vh, g_Vh);
    cudaGetSymbolAddress((void**)&p_hp, g_hp);
    cudaGetSymbolAddress((void**)&p_h,  g_h);
    cudaGetSymbolAddress((void**)&p_xs, g_xs);
    cudaGetSymbolAddress((void**)&p_cA, g_cA);
    cudaGetSymbolAddress((void**)&p_cB, g_cB);
    cudaGetSymbolAddress((void**)&p_aW, g_aW);
    cudaGetSymbolAddress((void**)&p_stats, g_stats);
    cudaGetSymbolAddress((void**)&p_hist, g_hist);
    cudaGetSymbolAddress((void**)&p_aux, g_aux);
    cudaGetSymbolAddress((void**)&p_peOff, g_peOff);
    cudaGetSymbolAddress((void**)&p_peCur, g_peCur);
    cudaGetSymbolAddress((void**)&p_peDst, g_peDst);
    cudaGetSymbolAddress((void**)&p_aOff, g_aOff);
    cudaGetSymbolAddress((void**)&p_aCur, g_aCur);
    cudaGetSymbolAddress((void**)&p_aSrc, g_aSrc);
    cudaGetSymbolAddress((void**)&p_pOff, g_pOff);
    cudaGetSymbolAddress((void**)&p_pCur, g_pCur);
    cudaGetSymbolAddress((void**)&p_pSort, g_pSort);
    cudaGetSymbolAddress((void**)&p_img, g_Bimg);
    cudaGetSymbolAddress((void**)&p_biasQV, g_biasQV);

    cudaFuncSetAttribute(gemm_mma_kernel, cudaFuncAttributeMaxDynamicSharedMemorySize, SM_GEMM);

    __nv_bfloat16* img_pre = (__nv_bfloat16*)p_img;                  // Kp=256, Nc=128
    __nv_bfloat16* img_qv0 = (__nv_bfloat16*)(p_img + 131072);       // Kp=128, Nc=256
    __nv_bfloat16* img_qv1 = (__nv_bfloat16*)(p_img + 262144);
    __nv_bfloat16* img_sf  = (__nv_bfloat16*)(p_img + 393216);       // Kp=128, Nc=128

    // ---- launches 1-3: prep images needed by the pre-GEMM ----
    prep_w_kernel<<<32, 256>>>(pre_W, C_, 256, img_pre);
    prep_qv_kernel<<<32, 256>>>(pf_Wq, pf_Wv, pf_bq, pf_bv, img_qv0, p_biasQV);
    prep_qv_kernel<<<32, 256>>>(pf_Wq + (size_t)2 * HID_ * 64, pf_Wv + (size_t)2 * HID_ * 64,
                                pf_bq + HID_, pf_bv + HID_, img_qv1, p_biasQV + 256);

    // ---- launch 4 (ncu capture slot): the pre GEMM ----
    gemm_mma_kernel<<<dim3(N_ / 128, 1), 256, SM_GEMM>>>(x, C_, 256, img_pre, 128,
                                                         pre_b, p_t0, (__half*)0);

    // ---- remaining preps + BN(x0) ----
    for (int l = 0; l < 5; l++)
        prep_w_kernel<<<16, 256>>>(sf_W + (size_t)l * HID_ * HID_, HID_, 128,
                                   img_sf + (size_t)l * 32768);
    run_bn(p_t0, p_x0, bn0_g, bn0_b, p_stats, N_, 0);

    // ---- sort pixel-graph edges by src -> CSR ----
    zero_kernel<<<N_ / 256, 256>>>(p_hist, N_);
    hist_kernel<<<EM_ / 256, 256>>>(m_src, EM_, p_hist);
    scan_block_kernel<<<N_ / 1024, 1024>>>(p_hist, N_, p_peOff, p_aux);
    scan_aux_kernel<<<1, 1024>>>(p_aux, N_ / 1024);
    scan_add_kernel<<<N_ / 256, 256>>>(p_peOff, N_, p_aux, p_peCur, EM_);
    scatter_edge_kernel<<<EM_ / 256, 256>>>(m_src, m_dst, EM_, p_peCur, p_peDst);

    // ---- sort superpixel-graph edges by dst -> CSR ----
    zero_kernel<<<S_ / 256, 256>>>(p_hist, S_);
    hist_kernel<<<EA_ / 256, 256>>>(a_dst, EA_, p_hist);
    scan_block_kernel<<<S_ / 1024, 1024>>>(p_hist, S_, p_aOff, p_aux);
    scan_aux_kernel<<<1, 1024>>>(p_aux, S_ / 1024);
    scan_add_kernel<<<S_ / 256, 256>>>(p_aOff, S_, p_aux, p_aCur, EA_);
    scatter_aedge_kernel<<<EA_ / 256, 256>>>(a_dst, a_src, a_w, EA_, p_aCur, p_aSrc, p_aW);

    // ---- sort pixels by seg -> CSR ----
    zero_kernel<<<S_ / 256, 256>>>(p_hist, S_);
    hist_kernel<<<N_ / 256, 256>>>(seg, N_, p_hist);
    scan_block_kernel<<<S_ / 1024, 1024>>>(p_hist, S_, p_pOff, p_aux);
    scan_aux_kernel<<<1, 1024>>>(p_aux, S_ / 1024);
    scan_add_kernel<<<S_ / 256, 256>>>(p_pOff, S_, p_aux, p_pCur, N_);
    scatter_pix_kernel<<<N_ / 256, 256>>>(seg, N_, p_pCur, p_pSort);

    // ---- PF branch: 2 attention layers on pixel graph ----
    const float* pfin = p_x0;
    for (int l = 0; l < 2; l++) {
        gemm_mma_kernel<<<dim3(N_ / 128, 2), 256, SM_GEMM>>>(pfin, HID_, 128,
                                                             (l == 0) ? img_qv0 : img_qv1, 256,
                                                             p_biasQV + l * 256, p_Q, p_Vh);
        ln_kernel<<<N_ / 8, 256>>>(p_Q, p_Qh);
        attn_kernel<<<N_ / 8, 256>>>(p_Qh, p_Vh, p_peOff, p_peDst, p_t0);
        run_bn(p_t0, p_pf, pf_g + l * HID_, pf_beta + l * HID_, p_stats, N_, 1);
        pfin = p_pf;
    }

    // ---- Hyperpixel branch: pool + 5 SF layers ----
    pool_kernel<<<S_ / 8, 256>>>(p_x0, p_pOff, p_pSort, p_hp);
    const float inv2g = 1.0f / 2.9f;
    for (int l = 0; l < 5; l++) {
        gemm_mma_kernel<<<dim3(S_ / 128, 1), 256, SM_GEMM>>>(p_hp, HID_, 128,
                                                             img_sf + (size_t)l * 32768, 128,
                                                             sf_b + l * HID_, p_h, (__half*)0);
        prop_kernel<<<S_ / 8, 256>>>(p_h, p_aOff, p_aSrc, p_aW, (const float*)0, 1.0f, p_xs);
        const float* cur = p_hp;
        float* nxt = p_cA;
        for (int it = 0; it < 5; it++) {
            prop_kernel<<<S_ / 8, 256>>>(cur, p_aOff, p_aSrc, p_aW, p_xs, inv2g, nxt);
            cur = nxt;
            nxt = (cur == p_cA) ? p_cB : p_cA;
        }
        run_bn(cur, p_hp, sf_g + l * HID_, sf_beta + l * HID_, p_stats, S_, 1);
    }

    // ---- final fused output ----
    final_kernel<<<N_ / 8, 256>>>(p_pf, p_hp, seg, out_W, out_b, out);
}

// round 17
// speedup vs baseline: 1.3608x; 1.0136x over previous
#include <cuda_runtime.h>
#include <cuda_bf16.h>
#include <cuda_fp16.h>
#include <cstdint>
#include <cstddef>
#include <math.h>

#define N_  262144
#define C_  200
#define HID_ 128
#define S_  4096
#define EA_ 65536
#define EM_ 2097152
#define NC_ 16

// ---------------- device scratch ----------------
__device__ float g_x0[(size_t)N_ * HID_];
__device__ float g_t0[(size_t)N_ * HID_];
__device__ float g_pf[(size_t)N_ * HID_];
__device__ float g_Q [(size_t)N_ * HID_];
__device__ __align__(16) __half g_Qh[(size_t)N_ * HID_];
__device__ __align__(16) __half g_Vh[(size_t)N_ * HID_];

__device__ float g_hp[S_ * HID_];
__device__ float g_h [S_ * HID_];
__device__ float g_xs[S_ * HID_];
__device__ float g_cA[S_ * HID_];
__device__ float g_cB[S_ * HID_];

__device__ int   g_hist[N_];
__device__ int   g_aux[1024];
__device__ int   g_peOff[N_ + 1];
__device__ int   g_peCur[N_];
__device__ int   g_peDst[EM_];
__device__ int   g_aOff[S_ + 1];
__device__ int   g_aCur[S_];
__device__ int   g_aSrc[EA_];
__device__ float g_aW [EA_];
__device__ int   g_pOff[S_ + 1];
__device__ int   g_pCur[S_];
__device__ int   g_pSort[N_];
__device__ float g_stats[256];

__device__ __align__(256) unsigned char g_Bimg[720896];
__device__ float g_biasQV[512];

// ---------------- split helpers ----------------
__device__ __forceinline__ void split4(float4 v, uint32_t& h01, uint32_t& h23,
                                       uint32_t& l01, uint32_t& l23) {
    __nv_bfloat16 h0 = __float2bfloat16(v.x), h1 = __float2bfloat16(v.y);
    __nv_bfloat16 h2 = __float2bfloat16(v.z), h3 = __float2bfloat16(v.w);
    __nv_bfloat16 l0 = __float2bfloat16(v.x - __bfloat162float(h0));
    __nv_bfloat16 l1 = __float2bfloat16(v.y - __bfloat162float(h1));
    __nv_bfloat16 l2 = __float2bfloat16(v.z - __bfloat162float(h2));
    __nv_bfloat16 l3 = __float2bfloat16(v.w - __bfloat162float(h3));
    h01 = ((uint32_t)__bfloat16_as_ushort(h1) << 16) | (uint32_t)__bfloat16_as_ushort(h0);
    h23 = ((uint32_t)__bfloat16_as_ushort(h3) << 16) | (uint32_t)__bfloat16_as_ushort(h2);
    l01 = ((uint32_t)__bfloat16_as_ushort(l1) << 16) | (uint32_t)__bfloat16_as_ushort(l0);
    l23 = ((uint32_t)__bfloat16_as_ushort(l3) << 16) | (uint32_t)__bfloat16_as_ushort(l2);
}

__device__ __forceinline__ void mma16816(float* c, const uint32_t* a, const uint32_t* b) {
    asm volatile(
        "mma.sync.aligned.m16n8k16.row.col.f32.bf16.bf16.f32 "
        "{%0,%1,%2,%3}, {%4,%5,%6,%7}, {%8,%9}, {%0,%1,%2,%3};"
        : "+f"(c[0]), "+f"(c[1]), "+f"(c[2]), "+f"(c[3])
        : "r"(a[0]), "r"(a[1]), "r"(a[2]), "r"(a[3]), "r"(b[0]), "r"(b[1]));
}

// ---------------- prep kernels ----------------
__global__ void prep_w_kernel(const float* __restrict__ W, int Kreal, int Kp,
                              __nv_bfloat16* __restrict__ img) {
    int idx = blockIdx.x * 256 + threadIdx.x;
    int kq = Kp >> 2;
    if (idx >= 128 * kq) return;
    int n = idx / kq;
    int k = (idx - n * kq) * 4;
    float4 v;
    v.x = (k + 0 < Kreal) ? W[(k + 0) * 128 + n] : 0.f;
    v.y = (k + 1 < Kreal) ? W[(k + 1) * 128 + n] : 0.f;
    v.z = (k + 2 < Kreal) ? W[(k + 2) * 128 + n] : 0.f;
    v.w = (k + 3 < Kreal) ? W[(k + 3) * 128 + n] : 0.f;
    uint32_t h01, h23, l01, l23;
    split4(v, h01, h23, l01, l23);
    *(uint2*)(img + (size_t)n * Kp + k)                    = make_uint2(h01, h23);
    *(uint2*)(img + (size_t)128 * Kp + (size_t)n * Kp + k) = make_uint2(l01, l23);
}

__global__ void prep_qv_kernel(const float* __restrict__ Wq, const float* __restrict__ Wv,
                               const float* __restrict__ bq, const float* __restrict__ bv,
                               __nv_bfloat16* __restrict__ img, float* __restrict__ biasOut) {
    int idx = blockIdx.x * 256 + threadIdx.x;
    if (idx >= 256 * 32) return;
    int n = idx >> 5;
    int k = (idx & 31) * 4;
    const float* W = (n < 128) ? Wq : Wv;
    int nn = (n < 128) ? n : n - 128;
    int h = nn >> 6, col = nn & 63;
    float4 v;
    v.x = W[((h * 128) + k + 0) * 64 + col];
    v.y = W[((h * 128) + k + 1) * 64 + col];
    v.z = W[((h * 128) + k + 2) * 64 + col];
    v.w = W[((h * 128) + k + 3) * 64 + col];
    uint32_t h01, h23, l01, l23;
    split4(v, h01, h23, l01, l23);
    *(uint2*)(img + (size_t)n * 128 + k)                     = make_uint2(h01, h23);
    *(uint2*)(img + (size_t)256 * 128 + (size_t)n * 128 + k) = make_uint2(l01, l23);
    if ((idx & 31) == 0) biasOut[n] = (n < 128) ? bq[h * 64 + col] : bv[h * 64 + col];
}

// ---------------- warp-MMA GEMM, double-buffered pipeline ----------------
// nh==0 writes float to outA; nh==1 writes __half to outBh.
#define LDA 72
#define STAGE_B (4 * 128 * LDA * 2)
#define SM_GEMM (2 * STAGE_B + 512)
__global__ __launch_bounds__(256) void gemm_mma_kernel(
    const float* __restrict__ A, int Kreal, int Kp,
    const __nv_bfloat16* __restrict__ Bimg, int Nc,
    const float* __restrict__ bias,
    float* __restrict__ outA, __half* __restrict__ outBh) {
    extern __shared__ char smem[];
    float* bsm = (float*)(smem + 2 * STAGE_B);
    int tid = threadIdx.x;
    int lane = tid & 31, wid = tid >> 5;
    int wm = wid & 3, wn = wid >> 2;
    long rowBase = (long)blockIdx.x * 128;
    int nh = blockIdx.y;
    const __nv_bfloat16* BsrcH = Bimg + (size_t)(nh * 128) * Kp;
    const __nv_bfloat16* BsrcL = Bimg + (size_t)Nc * Kp + (size_t)(nh * 128) * Kp;
    if (tid < 128) bsm[tid] = bias[nh * 128 + tid];

    int nch = Kp >> 6;
    int aRow = tid >> 4;
    int aCol0 = (tid & 15) * 4;

    float acc[2][8][4];
#pragma unroll
    for (int t = 0; t < 2; t++)
#pragma unroll
        for (int j = 0; j < 8; j++)
#pragma unroll
            for (int q = 0; q < 4; q++) acc[t][j][q] = 0.f;

    float4 aPre[8];
#pragma unroll
    for (int i = 0; i < 8; i++) {
        int row = aRow + i * 16;
        int k = aCol0;
        float4 v = make_float4(0.f, 0.f, 0.f, 0.f);
        if (k < Kreal) {
            const float* ap = A + (rowBase + row) * (long)Kreal + k;
            if (k + 3 < Kreal) v = *(const float4*)ap;
            else {
                v.x = ap[0];
                if (k + 1 < Kreal) v.y = ap[1];
                if (k + 2 < Kreal) v.z = ap[2];
            }
        }
        aPre[i] = v;
    }
    {
        char* st = smem;
        __nv_bfloat16* Bh = (__nv_bfloat16*)(st + 2 * 128 * LDA * 2);
        __nv_bfloat16* Bl = Bh + 128 * LDA;
#pragma unroll
        for (int i = 0; i < 8; i++) {
            int flat = tid + i * 256;
            int plane = flat >> 10;
            int r = (flat >> 3) & 127;
            int q = flat & 7;
            const __nv_bfloat16* src = (plane ? BsrcL : BsrcH) + (size_t)r * Kp + q * 8;
            __nv_bfloat16* dst = (plane ? Bl : Bh) + r * LDA + q * 8;
            uint32_t da = (uint32_t)__cvta_generic_to_shared(dst);
            asm volatile("cp.async.ca.shared.global [%0], [%1], 16;" :: "r"(da), "l"(src));
        }
        asm volatile("cp.async.commit_group;" ::: "memory");
    }

    for (int ch = 0; ch < nch; ch++) {
        int cur = ch & 1;
        char* st = smem + cur * STAGE_B;
        __nv_bfloat16* Ah = (__nv_bfloat16*)st;
        __nv_bfloat16* Al = Ah + 128 * LDA;
        __nv_bfloat16* Bh = Al + 128 * LDA;
        __nv_bfloat16* Bl = Bh + 128 * LDA;

#pragma unroll
        for (int i = 0; i < 8; i++) {
            int row = aRow + i * 16;
            uint32_t h01, h23, l01, l23;
            split4(aPre[i], h01, h23, l01, l23);
            *(uint2*)(Ah + row * LDA + aCol0) = make_uint2(h01, h23);
            *(uint2*)(Al + row * LDA + aCol0) = make_uint2(l01, l23);
        }
        if (ch + 1 < nch) {
#pragma unroll
            for (int i = 0; i < 8; i++) {
                int row = aRow + i * 16;
                int k = (ch + 1) * 64 + aCol0;
                float4 v = make_float4(0.f, 0.f, 0.f, 0.f);
                if (k < Kreal) {
                    const float* ap = A + (rowBase + row) * (long)Kreal + k;
                    if (k + 3 < Kreal) v = *(const float4*)ap;
                    else {
                        v.x = ap[0];
                        if (k + 1 < Kreal) v.y = ap[1];
                        if (k + 2 < Kreal) v.z = ap[2];
                    }
                }
                aPre[i] = v;
            }
        }
        asm volatile("cp.async.wait_group 0;" ::: "memory");
        __syncthreads();
        if (ch + 1 < nch) {
            char* st2 = smem + (1 - cur) * STAGE_B;
            __nv_bfloat16* Bh2 = (__nv_bfloat16*)(st2 + 2 * 128 * LDA * 2);
            __nv_bfloat16* Bl2 = Bh2 + 128 * LDA;
#pragma unroll
            for (int i = 0; i < 8; i++) {
                int flat = tid + i * 256;
                int plane = flat >> 10;
                int r = (flat >> 3) & 127;
                int q = flat & 7;
                const __nv_bfloat16* src = (plane ? BsrcL : BsrcH) + (size_t)r * Kp +
                                           (ch + 1) * 64 + q * 8;
                __nv_bfloat16* dst = (plane ? Bl2 : Bh2) + r * LDA + q * 8;
                uint32_t da = (uint32_t)__cvta_generic_to_shared(dst);
                asm volatile("cp.async.ca.shared.global [%0], [%1], 16;" :: "r"(da), "l"(src));
            }
            asm volatile("cp.async.commit_group;" ::: "memory");
        }

#pragma unroll
        for (int ks = 0; ks < 4; ks++) {
            int kk = ks * 16;
            uint32_t ah[2][4], al[2][4];
#pragma unroll
            for (int t = 0; t < 2; t++) {
                int r0 = wm * 32 + t * 16 + (lane >> 2);
                int cA = kk + (lane & 3) * 2;
                ah[t][0] = *(const uint32_t*)(Ah + r0 * LDA + cA);
                ah[t][1] = *(const uint32_t*)(Ah + (r0 + 8) * LDA + cA);
                ah[t][2] = *(const uint32_t*)(Ah + r0 * LDA + cA + 8);
                ah[t][3] = *(const uint32_t*)(Ah + (r0 + 8) * LDA + cA + 8);
                al[t][0] = *(const uint32_t*)(Al + r0 * LDA + cA);
                al[t][1] = *(const uint32_t*)(Al + (r0 + 8) * LDA + cA);
                al[t][2] = *(const uint32_t*)(Al + r0 * LDA + cA + 8);
                al[t][3] = *(const uint32_t*)(Al + (r0 + 8) * LDA + cA + 8);
            }
            uint32_t bh[8][2], bl[8][2];
#pragma unroll
            for (int j = 0; j < 8; j++) {
                int cn = wn * 64 + j * 8 + (lane >> 2);
                int cB = kk + (lane & 3) * 2;
                bh[j][0] = *(const uint32_t*)(Bh + cn * LDA + cB);
                bh[j][1] = *(const uint32_t*)(Bh + cn * LDA + cB + 8);
                bl[j][0] = *(const uint32_t*)(Bl + cn * LDA + cB);
                bl[j][1] = *(const uint32_t*)(Bl + cn * LDA + cB + 8);
            }
#pragma unroll
            for (int t = 0; t < 2; t++)
#pragma unroll
                for (int j = 0; j < 8; j++) {
                    mma16816(acc[t][j], ah[t], bh[j]);
                    mma16816(acc[t][j], al[t], bh[j]);
                    mma16816(acc[t][j], ah[t], bl[j]);
                }
        }
        __syncthreads();
    }

#pragma unroll
    for (int t = 0; t < 2; t++) {
        long r0 = rowBase + wm * 32 + t * 16 + (lane >> 2);
#pragma unroll
        for (int j = 0; j < 8; j++) {
            int cloc = wn * 64 + j * 8 + (lane & 3) * 2;
            float2 v0 = make_float2(acc[t][j][0] + bsm[cloc], acc[t][j][1] + bsm[cloc + 1]);
            float2 v1 = make_float2(acc[t][j][2] + bsm[cloc], acc[t][j][3] + bsm[cloc + 1]);
            if (nh == 0) {
                *(float2*)(outA + r0 * 128 + cloc)       = v0;
                *(float2*)(outA + (r0 + 8) * 128 + cloc) = v1;
            } else {
                *(__half2*)(outBh + r0 * 128 + cloc)       = __floats2half2_rn(v0.x, v0.y);
                *(__half2*)(outBh + (r0 + 8) * 128 + cloc) = __floats2half2_rn(v1.x, v1.y);
            }
        }
    }
}

// ---------------- utilities ----------------
__global__ void zero_kernel(int* p, int n) {
    int i = blockIdx.x * blockDim.x + threadIdx.x;
    if (i < n) p[i] = 0;
}
__global__ void zerof_kernel(float* p, int n) {
    int i = blockIdx.x * blockDim.x + threadIdx.x;
    if (i < n) p[i] = 0.f;
}

__global__ void hist_kernel(const int* __restrict__ keys, int n, int* __restrict__ hist) {
    int i = blockIdx.x * blockDim.x + threadIdx.x;
    if (i < n) atomicAdd(&hist[keys[i]], 1);
}

__global__ void scan_block_kernel(const int* __restrict__ in, int n,
                                  int* __restrict__ excl_out, int* __restrict__ bsum) {
    __shared__ int sh[1024];
    int tid = threadIdx.x;
    int idx = blockIdx.x * 1024 + tid;
    int v = (idx < n) ? in[idx] : 0;
    sh[tid] = v;
    __syncthreads();
    for (int off = 1; off < 1024; off <<= 1) {
        int t = (tid >= off) ? sh[tid - off] : 0;
        __syncthreads();
        sh[tid] += t;
        __syncthreads();
    }
    if (idx < n) excl_out[idx] = sh[tid] - v;
    if (tid == 1023) bsum[blockIdx.x] = sh[tid];
}

__global__ void scan_aux_kernel(int* aux, int nb) {
    __shared__ int sh[1024];
    int tid = threadIdx.x;
    int v = (tid < nb) ? aux[tid] : 0;
    sh[tid] = v;
    __syncthreads();
    for (int off = 1; off < 1024; off <<= 1) {
        int t = (tid >= off) ? sh[tid - off] : 0;
        __syncthreads();
        sh[tid] += t;
        __syncthreads();
    }
    if (tid < nb) aux[tid] = sh[tid] - v;
}

__global__ void scan_add_kernel(int* off, int n, const int* __restrict__ aux,
                                int* __restrict__ cursor, int total) {
    int idx = blockIdx.x * blockDim.x + threadIdx.x;
    if (idx < n) {
        int v = off[idx] + aux[idx >> 10];
        off[idx] = v;
        cursor[idx] = v;
    }
    if (idx == 0) off[n] = total;
}

__global__ void scatter_edge_kernel(const int* __restrict__ src, const int* __restrict__ dst,
                                    int n, int* __restrict__ cur, int* __restrict__ outDst) {
    int i = blockIdx.x * blockDim.x + threadIdx.x;
    if (i < n) {
        int p = atomicAdd(&cur[src[i]], 1);
        outDst[p] = dst[i];
    }
}

__global__ void scatter_aedge_kernel(const int* __restrict__ dstKey, const int* __restrict__ srcVal,
                                     const float* __restrict__ wVal, int n,
                                     int* __restrict__ cur, int* __restrict__ outSrc,
                                     float* __restrict__ outW) {
    int i = blockIdx.x * blockDim.x + threadIdx.x;
    if (i < n) {
        int p = atomicAdd(&cur[dstKey[i]], 1);
        outSrc[p] = srcVal[i];
        outW[p]   = wVal[i];
    }
}

__global__ void scatter_pix_kernel(const int* __restrict__ seg, int n,
                                   int* __restrict__ cur, int* __restrict__ outPix) {
    int i = blockIdx.x * blockDim.x + threadIdx.x;
    if (i < n) {
        int p = atomicAdd(&cur[seg[i]], 1);
        outPix[p] = i;
    }
}

// ---------------- BatchNorm ----------------
__global__ __launch_bounds__(256) void bnstats_kernel(const float* __restrict__ X, int M,
                                                      float* __restrict__ stats) {
    int lane = threadIdx.x & 31;
    int rs = threadIdx.x >> 5;
    float4 s = make_float4(0.f, 0.f, 0.f, 0.f);
    float4 q = make_float4(0.f, 0.f, 0.f, 0.f);
    for (long r = blockIdx.x * 8 + rs; r < M; r += (long)gridDim.x * 8) {
        float4 v = *(const float4*)(X + r * HID_ + lane * 4);
        s.x += v.x; s.y += v.y; s.z += v.z; s.w += v.w;
        q.x += v.x * v.x; q.y += v.y * v.y; q.z += v.z * v.z; q.w += v.w * v.w;
    }
    __shared__ float shs[8][HID_];
    __shared__ float shq[8][HID_];
    shs[rs][lane * 4 + 0] = s.x; shs[rs][lane * 4 + 1] = s.y;
    shs[rs][lane * 4 + 2] = s.z; shs[rs][lane * 4 + 3] = s.w;
    shq[rs][lane * 4 + 0] = q.x; shq[rs][lane * 4 + 1] = q.y;
    shq[rs][lane * 4 + 2] = q.z; shq[rs][lane * 4 + 3] = q.w;
    __syncthreads();
    if (threadIdx.x < HID_) {
        int c = threadIdx.x;
        float ss = 0.f, qq = 0.f;
#pragma unroll
        for (int r = 0; r < 8; r++) { ss += shs[r][c]; qq += shq[r][c]; }
        atomicAdd(&stats[c], ss);
        atomicAdd(&stats[HID_ + c], qq);
    }
}

__global__ void bnprep_kernel(float* stats, const float* __restrict__ g,
                              const float* __restrict__ b, float invM) {
    int c = threadIdx.x;
    float m = stats[c] * invM;
    float var = stats[HID_ + c] * invM - m * m;
    float w = rsqrtf(var + 1e-5f);
    float sc = w * g[c];
    stats[HID_ + c] = sc;
    stats[c] = b[c] - m * sc;
}

__global__ void bnapply_kernel(const float* __restrict__ X, float* __restrict__ Y,
                               const float* __restrict__ stats, long M, int lrelu) {
    long idx = (long)blockIdx.x * blockDim.x + threadIdx.x;
    long total = M * 32;
    if (idx >= total) return;
    int c4 = (int)(idx & 31);
    float4 v = *(const float4*)(X + idx * 4);
    float in[4] = {v.x, v.y, v.z, v.w};
    float o[4];
#pragma unroll
    for (int j = 0; j < 4; j++) {
        int c = c4 * 4 + j;
        float y = in[j] * stats[HID_ + c] + stats[c];
        if (lrelu) y = (y >= 0.f) ? y : 0.01f * y;
        o[j] = y;
    }
    *(float4*)(Y + idx * 4) = make_float4(o[0], o[1], o[2], o[3]);
}

// ---------------- LayerNorm per 64-wide head; outputs half ----------------
__global__ __launch_bounds__(256) void ln_kernel(const float* __restrict__ Q,
                                                 __half* __restrict__ Qh) {
    int wid = threadIdx.x >> 5, lane = threadIdx.x & 31;
    long row = (long)blockIdx.x * 8 + wid;
    float4 v = *(const float4*)(Q + row * HID_ + lane * 4);
    float s = v.x + v.y + v.z + v.w;
    float q = v.x * v.x + v.y * v.y + v.z * v.z + v.w * v.w;
#pragma unroll
    for (int o = 8; o >= 1; o >>= 1) {
        s += __shfl_xor_sync(0xffffffffu, s, o);
        q += __shfl_xor_sync(0xffffffffu, q, o);
    }
    float m = s * (1.0f / 64.0f);
    float var = q * (1.0f / 64.0f) - m * m;
    float w = rsqrtf(var + 1e-5f);
    __half2 a = __floats2half2_rn((v.x - m) * w, (v.y - m) * w);
    __half2 b = __floats2half2_rn((v.z - m) * w, (v.w - m) * w);
    uint2 o2;
    o2.x = *(uint32_t*)&a;
    o2.y = *(uint32_t*)&b;
    *(uint2*)(Qh + row * HID_ + lane * 4) = o2;
}

// ---------------- fused attention: SINGLE PASS (normalize by z at the end) ----------------
// half-warp per edge; out = (sum_i e_i * V_i) / (sum_i e_i)
__global__ __launch_bounds__(256) void attn_kernel(
    const __half* __restrict__ Q, const __half* __restrict__ V,
    const int* __restrict__ off, const int* __restrict__ dsts,
    float* __restrict__ out) {
    int tid = threadIdx.x;
    int wid = tid >> 5, lane = tid & 31;
    int hw = lane >> 4;          // half-warp id
    int hl = lane & 15;          // lane within half-warp
    unsigned hmask = hw ? 0xffff0000u : 0x0000ffffu;
    int src = blockIdx.x * 8 + wid;
    int o0 = off[src], o1 = off[src + 1];
    int deg = o1 - o0;

    uint4 qr = *(const uint4*)(Q + (long)src * HID_ + hl * 8);
    float qv[8];
    {
        __half2* qh = (__half2*)&qr;
#pragma unroll
        for (int k = 0; k < 4; k++) {
            float2 f = __half22float2(qh[k]);
            qv[2 * k] = f.x; qv[2 * k + 1] = f.y;
        }
    }

    float z = 0.f;
    float acc[8];
#pragma unroll
    for (int k = 0; k < 8; k++) acc[k] = 0.f;

    int nIter = (deg + 1) >> 1;
    for (int it = 0; it < nIter; it++) {
        int i = it * 2 + hw;
        bool valid = (i < deg);
        int d = dsts[o0 + (valid ? i : 0)];
        // issue both gathers up front (independent -> 2x MLP)
        uint4 dr = *(const uint4*)(Q + (long)d * HID_ + hl * 8);
        uint4 vr = *(const uint4*)(V + (long)d * HID_ + hl * 8);
        __half2* dh = (__half2*)&dr;
        float p = 0.f;
#pragma unroll
        for (int k = 0; k < 4; k++) {
            float2 f = __half22float2(dh[k]);
            p += qv[2 * k] * f.x + qv[2 * k + 1] * f.y;
        }
        p += __shfl_xor_sync(hmask, p, 4);
        p += __shfl_xor_sync(hmask, p, 2);
        p += __shfl_xor_sync(hmask, p, 1);
        float e = valid ? __expf(p * (1.0f / HID_)) : 0.f;
        z += e;
        __half2* vh = (__half2*)&vr;
#pragma unroll
        for (int k = 0; k < 4; k++) {
            float2 f = __half22float2(vh[k]);
            acc[2 * k]     += e * f.x;
            acc[2 * k + 1] += e * f.y;
        }
    }
    // combine across half-warps (warp fully converged: nIter is warp-uniform)
    z += __shfl_xor_sync(0xffffffffu, z, 16);
#pragma unroll
    for (int k = 0; k < 8; k++) acc[k] += __shfl_xor_sync(0xffffffffu, acc[k], 16);
    float invz = (deg > 0) ? 1.0f / z : 0.f;
    if (hw == 0) {
        long base = (long)src * HID_ + hl * 8;
        *(float4*)(out + base)     = make_float4(acc[0] * invz, acc[1] * invz,
                                                 acc[2] * invz, acc[3] * invz);
        *(float4*)(out + base + 4) = make_float4(acc[4] * invz, acc[5] * invz,
                                                 acc[6] * invz, acc[7] * invz);
    }
}

// ---------------- superpixel mean pooling ----------------
__global__ __launch_bounds__(256) void pool_kernel(const float* __restrict__ X,
                                                   const int* __restrict__ off,
                                                   const int* __restrict__ pix,
                                                   float* __restrict__ hp) {
    int wid = threadIdx.x >> 5, lane = threadIdx.x & 31;
    int s = blockIdx.x * 8 + wid;
    int o0 = off[s], o1 = off[s + 1];
    float4 acc = make_float4(0.f, 0.f, 0.f, 0.f);
    for (int i = o0; i < o1; i++) {
        int p = pix[i];
        float4 v = *(const float4*)(X + (long)p * HID_ + lane * 4);
        acc.x += v.x; acc.y += v.y; acc.z += v.z; acc.w += v.w;
    }
    int deg = o1 - o0;
    float inv = 1.0f / (float)(deg > 0 ? deg : 1);
    acc.x *= inv; acc.y *= inv; acc.z *= inv; acc.w *= inv;
    *(float4*)(hp + (long)s * HID_ + lane * 4) = acc;
}

// ---------------- weighted sparse prop (dst-CSR) ----------------
__global__ __launch_bounds__(256) void prop_kernel(const float* __restrict__ X,
                                                   const int* __restrict__ off,
                                                   const int* __restrict__ srcs,
                                                   const float* __restrict__ w,
                                                   const float* __restrict__ add, float scale,
                                                   float* __restrict__ out) {
    int wid = threadIdx.x >> 5, lane = threadIdx.x & 31;
    int d = blockIdx.x * 8 + wid;
    int o0 = off[d], o1 = off[d + 1];
    float4 acc = make_float4(0.f, 0.f, 0.f, 0.f);
    for (int i = o0; i < o1; i++) {
        int sN = srcs[i];
        float ww = w[i];
        float4 v = *(const float4*)(X + (long)sN * HID_ + lane * 4);
        acc.x += ww * v.x; acc.y += ww * v.y;
        acc.z += ww * v.z; acc.w += ww * v.w;
    }
    if (add) {
        float4 a = *(const float4*)(add + (long)d * HID_ + lane * 4);
        acc.x = (acc.x + a.x) * scale; acc.y = (acc.y + a.y) * scale;
        acc.z = (acc.z + a.z) * scale; acc.w = (acc.w + a.w) * scale;
    }
    *(float4*)(out + (long)d * HID_ + lane * 4) = acc;
}

// ---------------- final: softmax((pf + hp[seg]) @ W + b) ----------------
__global__ __launch_bounds__(256) void final_kernel(const float* __restrict__ PF,
                                                    const float* __restrict__ HP,
                                                    const int* __restrict__ seg,
                                                    const float* __restrict__ W,
                                                    const float* __restrict__ bias,
                                                    float* __restrict__ out) {
    __shared__ float Ws[HID_ * NC_];
    __shared__ float bs[NC_];
    for (int i = threadIdx.x; i < HID_ * NC_; i += 256) Ws[i] = W[i];
    if (threadIdx.x < NC_) bs[threadIdx.x] = bias[threadIdx.x];
    __syncthreads();
    int wid = threadIdx.x >> 5, lane = threadIdx.x & 31;
    long row = (long)blockIdx.x * 8 + wid;
    int sg = seg[row];
    float4 p4 = *(const float4*)(PF + row * HID_ + lane * 4);
    float4 h4 = *(const float4*)(HP + (long)sg * HID_ + lane * 4);
    float h[4] = {p4.x + h4.x, p4.y + h4.y, p4.z + h4.z, p4.w + h4.w};
    float l[NC_];
#pragma unroll
    for (int c = 0; c < NC_; c++) {
        l[c] = h[0] * Ws[(lane * 4 + 0) * NC_ + c] + h[1] * Ws[(lane * 4 + 1) * NC_ + c] +
               h[2] * Ws[(lane * 4 + 2) * NC_ + c] + h[3] * Ws[(lane * 4 + 3) * NC_ + c];
    }
#pragma unroll
    for (int o = 16; o >= 1; o >>= 1) {
#pragma unroll
        for (int c = 0; c < NC_; c++) l[c] += __shfl_xor_sync(0xffffffffu, l[c], o);
    }
    float mx = -1e30f;
#pragma unroll
    for (int c = 0; c < NC_; c++) {
        l[c] += bs[c];
        mx = fmaxf(mx, l[c]);
    }
    float sum = 0.f;
#pragma unroll
    for (int c = 0; c < NC_; c++) {
        l[c] = __expf(l[c] - mx);
        sum += l[c];
    }
    float inv = 1.0f / sum;
    if (lane < NC_) {
        float v = 0.f;
#pragma unroll
        for (int c = 0; c < NC_; c++)
            if (lane == c) v = l[c];
        out[row * NC_ + lane] = v * inv;
    }
}

// ---------------- host orchestration ----------------
static void run_bn(const float* X, float* Y, const float* g, const float* b,
                   float* stats, long M, int lrelu) {
    zerof_kernel<<<1, 256>>>(stats, 256);
    int nb = (M >= 100000) ? 1024 : 16;
    bnstats_kernel<<<nb, 256>>>(X, (int)M, stats);
    bnprep_kernel<<<1, 128>>>(stats, g, b, 1.0f / (float)M);
    long total = M * 32;
    bnapply_kernel<<<(int)((total + 255) / 256), 256>>>(X, Y, stats, M, lrelu);
}

extern "C" void kernel_launch(void* const* d_in, const int* in_sizes, int n_in,
                              void* d_out, int out_size) {
    const float* x      = (const float*)d_in[0];
    const int*   seg    = (const int*)d_in[1];
    const int*   a_src  = (const int*)d_in[2];
    const int*   a_dst  = (const int*)d_in[3];
    const float* a_w    = (const float*)d_in[4];
    const int*   m_src  = (const int*)d_in[5];
    const int*   m_dst  = (const int*)d_in[6];
    const float* pre_W  = (const float*)d_in[7];
    const float* pre_b  = (const float*)d_in[8];
    const float* bn0_g  = (const float*)d_in[9];
    const float* bn0_b  = (const float*)d_in[10];
    const float* sf_W   = (const float*)d_in[11];
    const float* sf_b   = (const float*)d_in[12];
    const float* sf_g   = (const float*)d_in[13];
    const float* sf_beta= (const float*)d_in[14];
    const float* pf_Wv  = (const float*)d_in[15];
    const float* pf_bv  = (const float*)d_in[16];
    const float* pf_Wq  = (const float*)d_in[17];
    const float* pf_bq  = (const float*)d_in[18];
    const float* pf_g   = (const float*)d_in[19];
    const float* pf_beta= (const float*)d_in[20];
    const float* out_W  = (const float*)d_in[21];
    const float* out_b  = (const float*)d_in[22];
    float* out = (float*)d_out;

    float *p_x0, *p_t0, *p_pf, *p_Q, *p_hp, *p_h, *p_xs, *p_cA, *p_cB, *p_aW, *p_stats, *p_biasQV;
    __half *p_Qh, *p_Vh;
    int *p_hist, *p_aux, *p_peOff, *p_peCur, *p_peDst, *p_aOff, *p_aCur, *p_aSrc;
    int *p_pOff, *p_pCur, *p_pSort;
    unsigned char* p_img;
    cudaGetSymbolAddress((void**)&p_x0, g_x0);
    cudaGetSymbolAddress((void**)&p_t0, g_t0);
    cudaGetSymbolAddress((void**)&p_pf, g_pf);
    cudaGetSymbolAddress((void**)&p_Q,  g_Q);
    cudaGetSymbolAddress((void**)&p_Qh, g_Qh);
    cudaGetSymbolAddress((void**)&p_Vh, g_Vh);
    cudaGetSymbolAddress((void**)&p_hp, g_hp);
    cudaGetSymbolAddress((void**)&p_h,  g_h);
    cudaGetSymbolAddress((void**)&p_xs, g_xs);
    cudaGetSymbolAddress((void**)&p_cA, g_cA);
    cudaGetSymbolAddress((void**)&p_cB, g_cB);
    cudaGetSymbolAddress((void**)&p_aW, g_aW);
    cudaGetSymbolAddress((void**)&p_stats, g_stats);
    cudaGetSymbolAddress((void**)&p_hist, g_hist);
    cudaGetSymbolAddress((void**)&p_aux, g_aux);
    cudaGetSymbolAddress((void**)&p_peOff, g_peOff);
    cudaGetSymbolAddress((void**)&p_peCur, g_peCur);
    cudaGetSymbolAddress((void**)&p_peDst, g_peDst);
    cudaGetSymbolAddress((void**)&p_aOff, g_aOff);
    cudaGetSymbolAddress((void**)&p_aCur, g_aCur);
    cudaGetSymbolAddress((void**)&p_aSrc, g_aSrc);
    cudaGetSymbolAddress((void**)&p_pOff, g_pOff);
    cudaGetSymbolAddress((void**)&p_pCur, g_pCur);
    cudaGetSymbolAddress((void**)&p_pSort, g_pSort);
    cudaGetSymbolAddress((void**)&p_img, g_Bimg);
    cudaGetSymbolAddress((void**)&p_biasQV, g_biasQV);

    cudaFuncSetAttribute(gemm_mma_kernel, cudaFuncAttributeMaxDynamicSharedMemorySize, SM_GEMM);

    __nv_bfloat16* img_pre = (__nv_bfloat16*)p_img;                  // Kp=256, Nc=128
    __nv_bfloat16* img_qv0 = (__nv_bfloat16*)(p_img + 131072);       // Kp=128, Nc=256
    __nv_bfloat16* img_qv1 = (__nv_bfloat16*)(p_img + 262144);
    __nv_bfloat16* img_sf  = (__nv_bfloat16*)(p_img + 393216);       // Kp=128, Nc=128

    // ---- launches 1-3: prep images needed by the pre-GEMM ----
    prep_w_kernel<<<32, 256>>>(pre_W, C_, 256, img_pre);
    prep_qv_kernel<<<32, 256>>>(pf_Wq, pf_Wv, pf_bq, pf_bv, img_qv0, p_biasQV);
    prep_qv_kernel<<<32, 256>>>(pf_Wq + (size_t)2 * HID_ * 64, pf_Wv + (size_t)2 * HID_ * 64,
                                pf_bq + HID_, pf_bv + HID_, img_qv1, p_biasQV + 256);

    // ---- launch 4 (ncu capture slot): the pre GEMM ----
    gemm_mma_kernel<<<dim3(N_ / 128, 1), 256, SM_GEMM>>>(x, C_, 256, img_pre, 128,
                                                         pre_b, p_t0, (__half*)0);

    // ---- remaining preps + BN(x0) ----
    for (int l = 0; l < 5; l++)
        prep_w_kernel<<<16, 256>>>(sf_W + (size_t)l * HID_ * HID_, HID_, 128,
                                   img_sf + (size_t)l * 32768);
    run_bn(p_t0, p_x0, bn0_g, bn0_b, p_stats, N_, 0);

    // ---- sort pixel-graph edges by src -> CSR ----
    zero_kernel<<<N_ / 256, 256>>>(p_hist, N_);
    hist_kernel<<<EM_ / 256, 256>>>(m_src, EM_, p_hist);
    scan_block_kernel<<<N_ / 1024, 1024>>>(p_hist, N_, p_peOff, p_aux);
    scan_aux_kernel<<<1, 1024>>>(p_aux, N_ / 1024);
    scan_add_kernel<<<N_ / 256, 256>>>(p_peOff, N_, p_aux, p_peCur, EM_);
    scatter_edge_kernel<<<EM_ / 256, 256>>>(m_src, m_dst, EM_, p_peCur, p_peDst);

    // ---- sort superpixel-graph edges by dst -> CSR ----
    zero_kernel<<<S_ / 256, 256>>>(p_hist, S_);
    hist_kernel<<<EA_ / 256, 256>>>(a_dst, EA_, p_hist);
    scan_block_kernel<<<S_ / 1024, 1024>>>(p_hist, S_, p_aOff, p_aux);
    scan_aux_kernel<<<1, 1024>>>(p_aux, S_ / 1024);
    scan_add_kernel<<<S_ / 256, 256>>>(p_aOff, S_, p_aux, p_aCur, EA_);
    scatter_aedge_kernel<<<EA_ / 256, 256>>>(a_dst, a_src, a_w, EA_, p_aCur, p_aSrc, p_aW);

    // ---- sort pixels by seg -> CSR ----
    zero_kernel<<<S_ / 256, 256>>>(p_hist, S_);
    hist_kernel<<<N_ / 256, 256>>>(seg, N_, p_hist);
    scan_block_kernel<<<S_ / 1024, 1024>>>(p_hist, S_, p_pOff, p_aux);
    scan_aux_kernel<<<1, 1024>>>(p_aux, S_ / 1024);
    scan_add_kernel<<<S_ / 256, 256>>>(p_pOff, S_, p_aux, p_pCur, N_);
    scatter_pix_kernel<<<N_ / 256, 256>>>(seg, N_, p_pCur, p_pSort);

    // ---- PF branch: 2 attention layers on pixel graph ----
    const float* pfin = p_x0;
    for (int l = 0; l < 2; l++) {
        gemm_mma_kernel<<<dim3(N_ / 128, 2), 256, SM_GEMM>>>(pfin, HID_, 128,
                                                             (l == 0) ? img_qv0 : img_qv1, 256,
                                                             p_biasQV + l * 256, p_Q, p_Vh);
        ln_kernel<<<N_ / 8, 256>>>(p_Q, p_Qh);
        attn_kernel<<<N_ / 8, 256>>>(p_Qh, p_Vh, p_peOff, p_peDst, p_t0);
        run_bn(p_t0, p_pf, pf_g + l * HID_, pf_beta + l * HID_, p_stats, N_, 1);
        pfin = p_pf;
    }

    // ---- Hyperpixel branch: pool + 5 SF layers ----
    pool_kernel<<<S_ / 8, 256>>>(p_x0, p_pOff, p_pSort, p_hp);
    const float inv2g = 1.0f / 2.9f;
    for (int l = 0; l < 5; l++) {
        gemm_mma_kernel<<<dim3(S_ / 128, 1), 256, SM_GEMM>>>(p_hp, HID_, 128,
                                                             img_sf + (size_t)l * 32768, 128,
                                                             sf_b + l * HID_, p_h, (__half*)0);
        prop_kernel<<<S_ / 8, 256>>>(p_h, p_aOff, p_aSrc, p_aW, (const float*)0, 1.0f, p_xs);
        const float* cur = p_hp;
        float* nxt = p_cA;
        for (int it = 0; it < 5; it++) {
            prop_kernel<<<S_ / 8, 256>>>(cur, p_aOff, p_aSrc, p_aW, p_xs, inv2g, nxt);
            cur = nxt;
            nxt = (cur == p_cA) ? p_cB : p_cA;
        }
        run_bn(cur, p_hp, sf_g + l * HID_, sf_beta + l * HID_, p_stats, S_, 1);
    }

    // ---- final fused output ----
    final_kernel<<<N_ / 8, 256>>>(p_pf, p_hp, seg, out_W, out_b, out);
}